// round 6
// baseline (speedup 1.0000x reference)
#include <cuda_runtime.h>
#include <math.h>

#define B_   2
#define S_   2048
#define LC_  1024
#define F_   1024
#define DC_  768
#define H_   16
#define HD_  64

// ---------------- scratch (no allocation allowed; zero-initialized) ----------------
__device__ __align__(16) float g_Qr[(size_t)B_ * S_ * F_];
__device__ __align__(16) float g_Qi[(size_t)B_ * S_ * F_];
__device__ __align__(16) float g_Kr[(size_t)B_ * LC_ * F_];
__device__ __align__(16) float g_Ki[(size_t)B_ * LC_ * F_];
__device__ __align__(16) float g_Vr[(size_t)B_ * LC_ * F_];
__device__ __align__(16) float g_Vi[(size_t)B_ * LC_ * F_];
__device__ __align__(16) float g_Or[(size_t)B_ * S_ * F_];
__device__ __align__(16) float g_Oi[(size_t)B_ * S_ * F_];

// ---------------- complex GEMM ----------------
// C = (Ar + iAi)(Br + iBi) + (br + i bi)
// A: M x K row-major, B: K x N row-major, C: M x N.
// 64x64 tile, K-step 16, 256 threads, 4x4 micro-tile. Static smem only.
// MODE 0: write g_Qr/g_Qi   MODE 1: g_Kr/g_Ki   MODE 2: g_Vr/g_Vi
// MODE 3: A = g_Or/g_Oi, write to output per omode:
//         omode 2 -> interleaved float2 (d_out has 2*M*N floats)
//         omode 1 -> real part only    (d_out has M*N floats)
template <int MODE>
__global__ void __launch_bounds__(256) cgemm_kernel(
    int M, int K, int N,
    const float* __restrict__ Ap_r, const float* __restrict__ Ap_i,
    const float* __restrict__ Br, const float* __restrict__ Bi,
    const float* __restrict__ bbr, const float* __restrict__ bbi,
    float* __restrict__ outF, int omode)
{
    const float* __restrict__ Ar = (MODE == 3) ? g_Or : Ap_r;
    const float* __restrict__ Ai = (MODE == 3) ? g_Oi : Ap_i;

    __shared__ __align__(16) float sAr[16][68];
    __shared__ __align__(16) float sAi[16][68];
    __shared__ __align__(16) float sBr[16][68];
    __shared__ __align__(16) float sBi[16][68];

    const int tid = threadIdx.x;
    const int tx = tid & 15;       // n group
    const int ty = tid >> 4;       // m group
    const int m0 = blockIdx.y << 6;
    const int n0 = blockIdx.x << 6;
    const int nl = tid & 63;       // B-load col
    const int kl = tid >> 6;       // B-load row base

    float accr[4][4] = {};
    float acci[4][4] = {};

    for (int k0 = 0; k0 < K; k0 += 16) {
#pragma unroll
        for (int j = 0; j < 4; j++) {
            int m = ty + j * 16;
            size_t g = (size_t)(m0 + m) * K + (k0 + tx);
            sAr[tx][m] = Ar[g];
            sAi[tx][m] = Ai[g];
        }
#pragma unroll
        for (int j = 0; j < 4; j++) {
            int kk = kl + j * 4;
            size_t g = (size_t)(k0 + kk) * N + (n0 + nl);
            sBr[kk][nl] = Br[g];
            sBi[kk][nl] = Bi[g];
        }
        __syncthreads();

#pragma unroll
        for (int kk = 0; kk < 16; kk++) {
            float4 arv = *(const float4*)&sAr[kk][ty * 4];
            float4 aiv = *(const float4*)&sAi[kk][ty * 4];
            float4 brv = *(const float4*)&sBr[kk][tx * 4];
            float4 biv = *(const float4*)&sBi[kk][tx * 4];
            float ar[4] = {arv.x, arv.y, arv.z, arv.w};
            float ai[4] = {aiv.x, aiv.y, aiv.z, aiv.w};
            float wr[4] = {brv.x, brv.y, brv.z, brv.w};
            float wi[4] = {biv.x, biv.y, biv.z, biv.w};
#pragma unroll
            for (int mm = 0; mm < 4; mm++) {
#pragma unroll
                for (int nn = 0; nn < 4; nn++) {
                    accr[mm][nn] = fmaf(ar[mm], wr[nn], accr[mm][nn]);
                    accr[mm][nn] = fmaf(-ai[mm], wi[nn], accr[mm][nn]);
                    acci[mm][nn] = fmaf(ar[mm], wi[nn], acci[mm][nn]);
                    acci[mm][nn] = fmaf(ai[mm], wr[nn], acci[mm][nn]);
                }
            }
        }
        __syncthreads();
    }

#pragma unroll
    for (int mm = 0; mm < 4; mm++) {
        int m = m0 + ty * 4 + mm;
#pragma unroll
        for (int nn = 0; nn < 4; nn++) {
            int n = n0 + tx * 4 + nn;
            float vr = accr[mm][nn] + (bbr ? bbr[n] : 0.0f);
            float vi = acci[mm][nn] + (bbi ? bbi[n] : 0.0f);
            size_t idx = (size_t)m * N + n;
            if (MODE == 0)      { g_Qr[idx] = vr; g_Qi[idx] = vi; }
            else if (MODE == 1) { g_Kr[idx] = vr; g_Ki[idx] = vi; }
            else if (MODE == 2) { g_Vr[idx] = vr; g_Vi[idx] = vi; }
            else {
                if (omode == 2) {
                    // d_out holds 2*M*N floats: interleaved (re, im)
                    outF[2 * idx]     = vr;
                    outF[2 * idx + 1] = vi;
                } else {
                    // d_out holds M*N floats: real part only (crash-proof fallback)
                    outF[idx] = vr;
                }
            }
        }
    }
}

// ---------------- attention (online softmax, static smem only) ----------------
// One block per (b, h, 32 q-rows). 256 threads. Key tiles of 32.
#define KT_ 32

__global__ void __launch_bounds__(256) attn_kernel(const float* __restrict__ mask)
{
    __shared__ __align__(16) float sQr[32 * 65];
    __shared__ __align__(16) float sQi[32 * 65];
    __shared__ __align__(16) float sKr[KT_ * 65];   // reused for Vr
    __shared__ __align__(16) float sKi[KT_ * 65];   // reused for Vi
    __shared__ float sP[32 * 33];
    __shared__ float sM[32], sL[32], sAlpha[32];

    const int tid = threadIdx.x;
    const int warp = tid >> 5, lane = tid & 31;
    const int q0 = blockIdx.x * 32;
    const int b = blockIdx.y >> 4;
    const int h = blockIdx.y & 15;

    for (int i = tid; i < 32 * HD_; i += 256) {
        int q = i >> 6, d = i & 63;
        size_t g = ((size_t)(b * S_ + q0 + q)) * F_ + h * HD_ + d;
        sQr[q * 65 + d] = g_Qr[g];
        sQi[q * 65 + d] = g_Qi[g];
    }
    if (tid < 32) { sM[tid] = -1e30f; sL[tid] = 0.0f; }

    const int row = tid >> 3;
    const int d0 = (tid & 7) * 8;
    float o_r[8] = {}, o_i[8] = {};

    const float scale = 0.125f;  // 1/sqrt(64)

    for (int kt = 0; kt < LC_ / KT_; kt++) {
        __syncthreads();
        for (int i = tid; i < KT_ * HD_; i += 256) {
            int k = i >> 6, d = i & 63;
            size_t g = ((size_t)(b * LC_ + kt * KT_ + k)) * F_ + h * HD_ + d;
            sKr[k * 65 + d] = g_Kr[g];
            sKi[k * 65 + d] = g_Ki[g];
        }
        __syncthreads();

        {
            const int r0 = warp * 4;
            float acc[4] = {0.f, 0.f, 0.f, 0.f};
#pragma unroll 8
            for (int d = 0; d < HD_; d++) {
                float kr = sKr[lane * 65 + d];
                float ki = sKi[lane * 65 + d];
#pragma unroll
                for (int r = 0; r < 4; r++) {
                    acc[r] = fmaf(sQr[(r0 + r) * 65 + d], kr, acc[r]);
                    acc[r] = fmaf(sQi[(r0 + r) * 65 + d], ki, acc[r]);
                }
            }
            float mv = mask ? ((1.0f - mask[b * LC_ + kt * KT_ + lane]) * -1e9f) : 0.0f;
#pragma unroll
            for (int r = 0; r < 4; r++) {
                int q = r0 + r;
                float s = acc[r] * scale + mv;
                float mx = s;
#pragma unroll
                for (int o = 16; o > 0; o >>= 1)
                    mx = fmaxf(mx, __shfl_xor_sync(0xffffffffu, mx, o));
                float m_old = sM[q];
                float m_new = fmaxf(m_old, mx);
                float p = __expf(s - m_new);
                float ps = p;
#pragma unroll
                for (int o = 16; o > 0; o >>= 1)
                    ps += __shfl_xor_sync(0xffffffffu, ps, o);
                sP[q * 33 + lane] = p;
                __syncwarp();
                if (lane == 0) {
                    float alpha = __expf(m_old - m_new);
                    sM[q] = m_new;
                    sL[q] = sL[q] * alpha + ps;
                    sAlpha[q] = alpha;
                }
                __syncwarp();
            }
        }
        __syncthreads();

        for (int i = tid; i < KT_ * HD_; i += 256) {
            int k = i >> 6, d = i & 63;
            size_t g = ((size_t)(b * LC_ + kt * KT_ + k)) * F_ + h * HD_ + d;
            sKr[k * 65 + d] = g_Vr[g];
            sKi[k * 65 + d] = g_Vi[g];
        }
        __syncthreads();

        float alpha = sAlpha[row];
#pragma unroll
        for (int j = 0; j < 8; j++) { o_r[j] *= alpha; o_i[j] *= alpha; }
#pragma unroll 4
        for (int k = 0; k < KT_; k++) {
            float p = sP[row * 33 + k];
#pragma unroll
            for (int j = 0; j < 8; j++) {
                o_r[j] = fmaf(p, sKr[k * 65 + d0 + j], o_r[j]);
                o_i[j] = fmaf(p, sKi[k * 65 + d0 + j], o_i[j]);
            }
        }
    }
    __syncthreads();

    float inv = 1.0f / sL[row];
    size_t g = ((size_t)(b * S_ + q0 + row)) * F_ + h * HD_ + d0;
#pragma unroll
    for (int j = 0; j < 8; j++) {
        g_Or[g + j] = o_r[j] * inv;
        g_Oi[g + j] = o_i[j] * inv;
    }
}

// Fallback: bounded zero-fill so graph capture always has nodes.
__global__ void fill_zero_kernel(float* p, long long n)
{
    long long i = (long long)blockIdx.x * blockDim.x + threadIdx.x;
    if (i < n) p[i] = 0.0f;
}

// ---------------- launch ----------------
extern "C" void kernel_launch(void* const* d_in, const int* in_sizes, int n_in,
                              void* d_out, int out_size)
{
    const long long MN = (long long)B_ * S_ * F_;   // 4,194,304 output elements (complex)

    // Size-based classification: robust to any cross-class permutation of
    // metadata order. Within a class, assume insertion order.
    const float* x4M[2]  = {0, 0}; int n4M = 0;   // x_r, x_i        (4194304)
    const float* xctx[2] = {0, 0}; int nctx = 0;  // ctx_r, ctx_i    (1572864)
    const float* pmask   = 0;                     // mask            (2048)
    const float* wF[4]   = {0, 0, 0, 0}; int nwF = 0;  // Wqr,Wqi,Wor,Woi (1048576)
    const float* wC[4]   = {0, 0, 0, 0}; int nwC = 0;  // Wkr,Wki,Wvr,Wvi (786432)
    const float* bias[8] = {0, 0, 0, 0, 0, 0, 0, 0}; int nb = 0;  // 8 x (1024)

    for (int i = 0; i < n_in; i++) {
        const float* p = (const float*)d_in[i];
        long long sz = in_sizes[i];
        if (sz == (long long)B_ * S_ * F_)        { if (n4M < 2) x4M[n4M++] = p; }
        else if (sz == (long long)B_ * LC_ * DC_) { if (nctx < 2) xctx[nctx++] = p; }
        else if (sz == (long long)B_ * LC_)       { pmask = p; }
        else if (sz == (long long)F_ * F_)        { if (nwF < 4) wF[nwF++] = p; }
        else if (sz == (long long)DC_ * F_)       { if (nwC < 4) wC[nwC++] = p; }
        else if (sz == (long long)F_)             { if (nb < 8) bias[nb++] = p; }
    }

    const float* x_r = x4M[0],  *x_i = x4M[1];
    const float* ctx_r = xctx[0], *ctx_i = xctx[1];
    const float* Wqr = wF[0], *Wqi = wF[1], *Wor = wF[2], *Woi = wF[3];
    const float* Wkr = wC[0], *Wki = wC[1], *Wvr = wC[2], *Wvi = wC[3];
    const float* bqr = bias[0], *bqi = bias[1];
    const float* bkr = bias[2], *bki = bias[3];
    const float* bvr = bias[4], *bvi = bias[5];
    const float* bor = bias[6], *boi = bias[7];

    // Output mode from the harness-provided out_size (ground truth):
    //   out_size == 2*MN -> 8M float elements, interleaved complex view
    //   otherwise        -> assume MN float elements, write real part only
    //                       (crash-proof; produces a rel_err signal if wrong)
    int omode = ((long long)out_size >= 2 * MN) ? 2 : 1;

    if (!x_r || !x_i || !ctx_r || !ctx_i || !Wqr || !Wqi || !Wor || !Woi ||
        !Wkr || !Wki || !Wvr || !Wvi) {
        // Classification failed: bounded zero-fill keeps capture non-empty
        // and makes this failure mode distinguishable from a crash.
        long long n = (omode == 2) ? 2 * MN : MN;
        fill_zero_kernel<<<(unsigned)((n + 255) / 256), 256>>>((float*)d_out, n);
        return;
    }

    dim3 blk(256);

    // Q = x @ Wq   (4096 x 1024 -> 1024)
    cgemm_kernel<0><<<dim3(F_ / 64, (B_ * S_) / 64), blk>>>(
        B_ * S_, F_, F_, x_r, x_i, Wqr, Wqi, bqr, bqi, nullptr, 0);
    // K = ctx @ Wk (2048 x 768 -> 1024)
    cgemm_kernel<1><<<dim3(F_ / 64, (B_ * LC_) / 64), blk>>>(
        B_ * LC_, DC_, F_, ctx_r, ctx_i, Wkr, Wki, bkr, bki, nullptr, 0);
    // V = ctx @ Wv
    cgemm_kernel<2><<<dim3(F_ / 64, (B_ * LC_) / 64), blk>>>(
        B_ * LC_, DC_, F_, ctx_r, ctx_i, Wvr, Wvi, bvr, bvi, nullptr, 0);

    // attention (reads g_Q*, g_K*, g_V*; writes g_O*)
    attn_kernel<<<dim3(S_ / 32, B_ * H_), blk>>>(pmask);

    // y = O @ Wo -> output (adaptive layout)
    cgemm_kernel<3><<<dim3(F_ / 64, (B_ * S_) / 64), blk>>>(
        B_ * S_, F_, F_, nullptr, nullptr, Wor, Woi, bor, boi, (float*)d_out, omode);
}

// round 7
// speedup vs baseline: 1.3325x; 1.3325x over previous
#include <cuda_runtime.h>
#include <math.h>
#include <stdint.h>

#define B_   2
#define S_   2048
#define LC_  1024
#define F_   1024
#define DC_  768
#define H_   16
#define HD_  64

// ---------------- scratch (no allocation allowed; zero-initialized) ----------------
__device__ __align__(16) float g_Qr[(size_t)B_ * S_ * F_];
__device__ __align__(16) float g_Qi[(size_t)B_ * S_ * F_];
__device__ __align__(16) float g_Kr[(size_t)B_ * LC_ * F_];
__device__ __align__(16) float g_Ki[(size_t)B_ * LC_ * F_];
__device__ __align__(16) float g_Vr[(size_t)B_ * LC_ * F_];
__device__ __align__(16) float g_Vi[(size_t)B_ * LC_ * F_];
__device__ __align__(16) float g_Or[(size_t)B_ * S_ * F_];
__device__ __align__(16) float g_Oi[(size_t)B_ * S_ * F_];

// ---------------- tf32 mma helpers ----------------
__device__ __forceinline__ uint32_t f2tf32(float x) {
    uint32_t r;
    asm("cvt.rna.tf32.f32 %0, %1;" : "=r"(r) : "f"(x));
    return r;
}

__device__ __forceinline__ void mma_tf32(float c[4], const uint32_t a[4], const uint32_t b[2]) {
    asm volatile(
        "mma.sync.aligned.m16n8k8.row.col.f32.tf32.tf32.f32 "
        "{%0,%1,%2,%3}, {%4,%5,%6,%7}, {%8,%9}, {%0,%1,%2,%3};"
        : "+f"(c[0]), "+f"(c[1]), "+f"(c[2]), "+f"(c[3])
        : "r"(a[0]), "r"(a[1]), "r"(a[2]), "r"(a[3]), "r"(b[0]), "r"(b[1]));
}

// ---------------- complex GEMM via tf32 tensor cores ----------------
// C = (Ar + iAi)(Br + iBi) + bias.  A: MxK row-major, B: KxN row-major.
// Block 64x64, K-step 16, 256 threads = 8 warps (2 warpM x 4 warpN),
// warp tile 32(m) x 16(n) = 2x2 m16n8k8 atoms.
// MODE 0: write g_Qr/g_Qi  MODE 1: g_Kr/g_Ki  MODE 2: g_Vr/g_Vi
// MODE 3: A = g_Or/g_Oi, write output (omode 2: interleaved, 1: real only)
#define SA_ST 20
#define SB_ST 72

template <int MODE>
__global__ void __launch_bounds__(256) cgemm_kernel(
    int M, int K, int N,
    const float* __restrict__ Ap_r, const float* __restrict__ Ap_i,
    const float* __restrict__ Br, const float* __restrict__ Bi,
    const float* __restrict__ bbr, const float* __restrict__ bbi,
    float* __restrict__ outF, int omode)
{
    const float* __restrict__ Ar = (MODE == 3) ? g_Or : Ap_r;
    const float* __restrict__ Ai = (MODE == 3) ? g_Oi : Ap_i;

    __shared__ float sAr[64 * SA_ST];
    __shared__ float sAi[64 * SA_ST];
    __shared__ float sBr[16 * SB_ST];
    __shared__ float sBi[16 * SB_ST];

    const int tid = threadIdx.x;
    const int warp = tid >> 5, lane = tid & 31;
    const int qrow = lane >> 2, qk = lane & 3;
    const int warpM = warp >> 2;       // 0..1 -> m offset *32
    const int warpN = warp & 3;        // 0..3 -> n offset *16
    const int m0 = blockIdx.y << 6;
    const int n0 = blockIdx.x << 6;

    float accr[2][2][4] = {};
    float acci[2][2][4] = {};

    const int lm = tid >> 4;       // A-load row within pass (16 rows/pass)
    const int lk = tid & 15;       // A-load k
    const int bn = tid & 63;       // B-load col
    const int bk = tid >> 6;       // B-load row base

    for (int k0 = 0; k0 < K; k0 += 16) {
#pragma unroll
        for (int j = 0; j < 4; j++) {
            int m = lm + j * 16;
            size_t g = (size_t)(m0 + m) * K + (k0 + lk);
            sAr[m * SA_ST + lk] = Ar[g];
            sAi[m * SA_ST + lk] = Ai[g];
        }
#pragma unroll
        for (int j = 0; j < 4; j++) {
            int kk = bk + j * 4;
            size_t g = (size_t)(k0 + kk) * N + (n0 + bn);
            sBr[kk * SB_ST + bn] = Br[g];
            sBi[kk * SB_ST + bn] = Bi[g];
        }
        __syncthreads();

#pragma unroll
        for (int kc = 0; kc < 16; kc += 8) {
            // A fragments (r, i) for 2 m-atoms
            uint32_t a_r[2][4], a_i[2][4];
#pragma unroll
            for (int ma = 0; ma < 2; ma++) {
                int mb = warpM * 32 + ma * 16 + qrow;
                a_r[ma][0] = f2tf32(sAr[(mb)     * SA_ST + kc + qk]);
                a_r[ma][1] = f2tf32(sAr[(mb + 8) * SA_ST + kc + qk]);
                a_r[ma][2] = f2tf32(sAr[(mb)     * SA_ST + kc + qk + 4]);
                a_r[ma][3] = f2tf32(sAr[(mb + 8) * SA_ST + kc + qk + 4]);
                a_i[ma][0] = f2tf32(sAi[(mb)     * SA_ST + kc + qk]);
                a_i[ma][1] = f2tf32(sAi[(mb + 8) * SA_ST + kc + qk]);
                a_i[ma][2] = f2tf32(sAi[(mb)     * SA_ST + kc + qk + 4]);
                a_i[ma][3] = f2tf32(sAi[(mb + 8) * SA_ST + kc + qk + 4]);
            }
            // B fragments (r, i, -i) for 2 n-atoms
            uint32_t b_r[2][2], b_i[2][2], b_ni[2][2];
#pragma unroll
            for (int na = 0; na < 2; na++) {
                int nb2 = warpN * 16 + na * 8 + qrow;
                float v0r = sBr[(kc + qk)     * SB_ST + nb2];
                float v1r = sBr[(kc + qk + 4) * SB_ST + nb2];
                float v0i = sBi[(kc + qk)     * SB_ST + nb2];
                float v1i = sBi[(kc + qk + 4) * SB_ST + nb2];
                b_r[na][0]  = f2tf32(v0r);
                b_r[na][1]  = f2tf32(v1r);
                b_i[na][0]  = f2tf32(v0i);
                b_i[na][1]  = f2tf32(v1i);
                b_ni[na][0] = f2tf32(-v0i);
                b_ni[na][1] = f2tf32(-v1i);
            }
#pragma unroll
            for (int ma = 0; ma < 2; ma++) {
#pragma unroll
                for (int na = 0; na < 2; na++) {
                    mma_tf32(accr[ma][na], a_r[ma], b_r[na]);
                    mma_tf32(accr[ma][na], a_i[ma], b_ni[na]);
                    mma_tf32(acci[ma][na], a_r[ma], b_i[na]);
                    mma_tf32(acci[ma][na], a_i[ma], b_r[na]);
                }
            }
        }
        __syncthreads();
    }

    // epilogue
#pragma unroll
    for (int ma = 0; ma < 2; ma++) {
#pragma unroll
        for (int na = 0; na < 2; na++) {
#pragma unroll
            for (int c = 0; c < 4; c++) {
                int row = m0 + warpM * 32 + ma * 16 + qrow + ((c >= 2) ? 8 : 0);
                int col = n0 + warpN * 16 + na * 8 + qk * 2 + (c & 1);
                float vr = accr[ma][na][c] + (bbr ? bbr[col] : 0.0f);
                float vi = acci[ma][na][c] + (bbi ? bbi[col] : 0.0f);
                size_t idx = (size_t)row * N + col;
                if (MODE == 0)      { g_Qr[idx] = vr; g_Qi[idx] = vi; }
                else if (MODE == 1) { g_Kr[idx] = vr; g_Ki[idx] = vi; }
                else if (MODE == 2) { g_Vr[idx] = vr; g_Vi[idx] = vi; }
                else {
                    if (omode == 2) { outF[2 * idx] = vr; outF[2 * idx + 1] = vi; }
                    else            { outF[idx] = vr; }
                }
            }
        }
    }
}

// ---------------- attention (online softmax, fp32, vectorized smem) ----------------
// One block per (b, h, 32 q-rows). 256 threads. Key tiles of 32. Stride 68
// (multiple of 4 -> LDS.128; 68 mod 32 = 4 -> conflict-free row spread).
#define KT_ 32
#define AST 68

__global__ void __launch_bounds__(256) attn_kernel(const float* __restrict__ mask)
{
    __shared__ __align__(16) float sQr[32 * AST];
    __shared__ __align__(16) float sQi[32 * AST];
    __shared__ __align__(16) float sKr[KT_ * AST];   // reused for Vr
    __shared__ __align__(16) float sKi[KT_ * AST];   // reused for Vi
    __shared__ float sP[32 * 33];
    __shared__ float sM[32], sL[32], sAlpha[32];

    const int tid = threadIdx.x;
    const int warp = tid >> 5, lane = tid & 31;
    const int q0 = blockIdx.x * 32;
    const int b = blockIdx.y >> 4;
    const int h = blockIdx.y & 15;

    for (int i = tid; i < 32 * (HD_ / 4); i += 256) {
        int q = i >> 4;
        int d4 = (i & 15) * 4;
        size_t g = ((size_t)(b * S_ + q0 + q)) * F_ + h * HD_ + d4;
        *(float4*)&sQr[q * AST + d4] = *(const float4*)&g_Qr[g];
        *(float4*)&sQi[q * AST + d4] = *(const float4*)&g_Qi[g];
    }
    if (tid < 32) { sM[tid] = -1e30f; sL[tid] = 0.0f; }

    const int row = tid >> 3;
    const int d0 = (tid & 7) * 8;
    float o_r[8] = {}, o_i[8] = {};

    const float scale = 0.125f;  // 1/sqrt(64)

    for (int kt = 0; kt < LC_ / KT_; kt++) {
        __syncthreads();
        for (int i = tid; i < KT_ * (HD_ / 4); i += 256) {
            int k = i >> 4;
            int d4 = (i & 15) * 4;
            size_t g = ((size_t)(b * LC_ + kt * KT_ + k)) * F_ + h * HD_ + d4;
            *(float4*)&sKr[k * AST + d4] = *(const float4*)&g_Kr[g];
            *(float4*)&sKi[k * AST + d4] = *(const float4*)&g_Ki[g];
        }
        __syncthreads();

        {
            const int r0 = warp * 4;
            float acc[4] = {0.f, 0.f, 0.f, 0.f};
#pragma unroll
            for (int d = 0; d < HD_; d += 4) {
                float4 kr = *(const float4*)&sKr[lane * AST + d];
                float4 ki = *(const float4*)&sKi[lane * AST + d];
#pragma unroll
                for (int r = 0; r < 4; r++) {
                    float4 qr = *(const float4*)&sQr[(r0 + r) * AST + d];
                    float4 qi = *(const float4*)&sQi[(r0 + r) * AST + d];
                    float a = acc[r];
                    a = fmaf(qr.x, kr.x, a); a = fmaf(qr.y, kr.y, a);
                    a = fmaf(qr.z, kr.z, a); a = fmaf(qr.w, kr.w, a);
                    a = fmaf(qi.x, ki.x, a); a = fmaf(qi.y, ki.y, a);
                    a = fmaf(qi.z, ki.z, a); a = fmaf(qi.w, ki.w, a);
                    acc[r] = a;
                }
            }
            float mv = mask ? ((1.0f - mask[b * LC_ + kt * KT_ + lane]) * -1e9f) : 0.0f;
#pragma unroll
            for (int r = 0; r < 4; r++) {
                int q = r0 + r;
                float s = acc[r] * scale + mv;
                float mx = s;
#pragma unroll
                for (int o = 16; o > 0; o >>= 1)
                    mx = fmaxf(mx, __shfl_xor_sync(0xffffffffu, mx, o));
                float m_old = sM[q];
                float m_new = fmaxf(m_old, mx);
                float p = __expf(s - m_new);
                float ps = p;
#pragma unroll
                for (int o = 16; o > 0; o >>= 1)
                    ps += __shfl_xor_sync(0xffffffffu, ps, o);
                sP[q * 33 + lane] = p;
                __syncwarp();
                if (lane == 0) {
                    float alpha = __expf(m_old - m_new);
                    sM[q] = m_new;
                    sL[q] = sL[q] * alpha + ps;
                    sAlpha[q] = alpha;
                }
                __syncwarp();
            }
        }
        __syncthreads();

        for (int i = tid; i < KT_ * (HD_ / 4); i += 256) {
            int k = i >> 4;
            int d4 = (i & 15) * 4;
            size_t g = ((size_t)(b * LC_ + kt * KT_ + k)) * F_ + h * HD_ + d4;
            *(float4*)&sKr[k * AST + d4] = *(const float4*)&g_Vr[g];
            *(float4*)&sKi[k * AST + d4] = *(const float4*)&g_Vi[g];
        }
        __syncthreads();

        float alpha = sAlpha[row];
#pragma unroll
        for (int j = 0; j < 8; j++) { o_r[j] *= alpha; o_i[j] *= alpha; }
#pragma unroll 4
        for (int k = 0; k < KT_; k++) {
            float p = sP[row * 33 + k];
            float4 vr0 = *(const float4*)&sKr[k * AST + d0];
            float4 vr1 = *(const float4*)&sKr[k * AST + d0 + 4];
            float4 vi0 = *(const float4*)&sKi[k * AST + d0];
            float4 vi1 = *(const float4*)&sKi[k * AST + d0 + 4];
            o_r[0] = fmaf(p, vr0.x, o_r[0]); o_r[1] = fmaf(p, vr0.y, o_r[1]);
            o_r[2] = fmaf(p, vr0.z, o_r[2]); o_r[3] = fmaf(p, vr0.w, o_r[3]);
            o_r[4] = fmaf(p, vr1.x, o_r[4]); o_r[5] = fmaf(p, vr1.y, o_r[5]);
            o_r[6] = fmaf(p, vr1.z, o_r[6]); o_r[7] = fmaf(p, vr1.w, o_r[7]);
            o_i[0] = fmaf(p, vi0.x, o_i[0]); o_i[1] = fmaf(p, vi0.y, o_i[1]);
            o_i[2] = fmaf(p, vi0.z, o_i[2]); o_i[3] = fmaf(p, vi0.w, o_i[3]);
            o_i[4] = fmaf(p, vi1.x, o_i[4]); o_i[5] = fmaf(p, vi1.y, o_i[5]);
            o_i[6] = fmaf(p, vi1.z, o_i[6]); o_i[7] = fmaf(p, vi1.w, o_i[7]);
        }
    }
    __syncthreads();

    float inv = 1.0f / sL[row];
    size_t g = ((size_t)(b * S_ + q0 + row)) * F_ + h * HD_ + d0;
#pragma unroll
    for (int j = 0; j < 8; j++) {
        g_Or[g + j] = o_r[j] * inv;
        g_Oi[g + j] = o_i[j] * inv;
    }
}

// Fallback: bounded zero-fill so graph capture always has nodes.
__global__ void fill_zero_kernel(float* p, long long n)
{
    long long i = (long long)blockIdx.x * blockDim.x + threadIdx.x;
    if (i < n) p[i] = 0.0f;
}

// ---------------- launch ----------------
extern "C" void kernel_launch(void* const* d_in, const int* in_sizes, int n_in,
                              void* d_out, int out_size)
{
    const long long MN = (long long)B_ * S_ * F_;   // 4,194,304 complex outputs

    const float* x4M[2]  = {0, 0}; int n4M = 0;   // x_r, x_i        (4194304)
    const float* xctx[2] = {0, 0}; int nctx = 0;  // ctx_r, ctx_i    (1572864)
    const float* pmask   = 0;                     // mask            (2048)
    const float* wF[4]   = {0, 0, 0, 0}; int nwF = 0;  // Wqr,Wqi,Wor,Woi (1048576)
    const float* wC[4]   = {0, 0, 0, 0}; int nwC = 0;  // Wkr,Wki,Wvr,Wvi (786432)
    const float* bias[8] = {0, 0, 0, 0, 0, 0, 0, 0}; int nb = 0;  // 8 x (1024)

    for (int i = 0; i < n_in; i++) {
        const float* p = (const float*)d_in[i];
        long long sz = in_sizes[i];
        if (sz == (long long)B_ * S_ * F_)        { if (n4M < 2) x4M[n4M++] = p; }
        else if (sz == (long long)B_ * LC_ * DC_) { if (nctx < 2) xctx[nctx++] = p; }
        else if (sz == (long long)B_ * LC_)       { pmask = p; }
        else if (sz == (long long)F_ * F_)        { if (nwF < 4) wF[nwF++] = p; }
        else if (sz == (long long)DC_ * F_)       { if (nwC < 4) wC[nwC++] = p; }
        else if (sz == (long long)F_)             { if (nb < 8) bias[nb++] = p; }
    }

    const float* x_r = x4M[0],  *x_i = x4M[1];
    const float* ctx_r = xctx[0], *ctx_i = xctx[1];
    const float* Wqr = wF[0], *Wqi = wF[1], *Wor = wF[2], *Woi = wF[3];
    const float* Wkr = wC[0], *Wki = wC[1], *Wvr = wC[2], *Wvi = wC[3];
    const float* bqr = bias[0], *bqi = bias[1];
    const float* bkr = bias[2], *bki = bias[3];
    const float* bvr = bias[4], *bvi = bias[5];
    const float* bor = bias[6], *boi = bias[7];

    int omode = ((long long)out_size >= 2 * MN) ? 2 : 1;

    if (!x_r || !x_i || !ctx_r || !ctx_i || !Wqr || !Wqi || !Wor || !Woi ||
        !Wkr || !Wki || !Wvr || !Wvi) {
        long long n = (omode == 2) ? 2 * MN : MN;
        fill_zero_kernel<<<(unsigned)((n + 255) / 256), 256>>>((float*)d_out, n);
        return;
    }

    dim3 blk(256);

    // Q = x @ Wq   (4096 x 1024 -> 1024)
    cgemm_kernel<0><<<dim3(F_ / 64, (B_ * S_) / 64), blk>>>(
        B_ * S_, F_, F_, x_r, x_i, Wqr, Wqi, bqr, bqi, nullptr, 0);
    // K = ctx @ Wk (2048 x 768 -> 1024)
    cgemm_kernel<1><<<dim3(F_ / 64, (B_ * LC_) / 64), blk>>>(
        B_ * LC_, DC_, F_, ctx_r, ctx_i, Wkr, Wki, bkr, bki, nullptr, 0);
    // V = ctx @ Wv
    cgemm_kernel<2><<<dim3(F_ / 64, (B_ * LC_) / 64), blk>>>(
        B_ * LC_, DC_, F_, ctx_r, ctx_i, Wvr, Wvi, bvr, bvi, nullptr, 0);

    // attention (reads g_Q*, g_K*, g_V*; writes g_O*)
    attn_kernel<<<dim3(S_ / 32, B_ * H_), blk>>>(pmask);

    // y = O @ Wo -> output (adaptive layout)
    cgemm_kernel<3><<<dim3(F_ / 64, (B_ * S_) / 64), blk>>>(
        B_ * S_, F_, F_, nullptr, nullptr, Wor, Woi, bor, boi, (float*)d_out, omode);
}

// round 8
// speedup vs baseline: 1.3884x; 1.0420x over previous
#include <cuda_runtime.h>
#include <math.h>
#include <stdint.h>

#define B_   2
#define S_   2048
#define LC_  1024
#define F_   1024
#define DC_  768
#define H_   16
#define HD_  64

// ---------------- scratch (no allocation allowed; zero-initialized) ----------------
__device__ __align__(16) float g_Qr[(size_t)B_ * S_ * F_];
__device__ __align__(16) float g_Qi[(size_t)B_ * S_ * F_];
__device__ __align__(16) float g_Kr[(size_t)B_ * LC_ * F_];
__device__ __align__(16) float g_Ki[(size_t)B_ * LC_ * F_];
__device__ __align__(16) float g_Vr[(size_t)B_ * LC_ * F_];
__device__ __align__(16) float g_Vi[(size_t)B_ * LC_ * F_];
__device__ __align__(16) float g_Or[(size_t)B_ * S_ * F_];
__device__ __align__(16) float g_Oi[(size_t)B_ * S_ * F_];

// ---------------- tf32 mma helpers ----------------
__device__ __forceinline__ uint32_t f2tf32(float x) {
    uint32_t r;
    asm("cvt.rna.tf32.f32 %0, %1;" : "=r"(r) : "f"(x));
    return r;
}

__device__ __forceinline__ void mma_tf32(float c[4], const uint32_t a[4], const uint32_t b[2]) {
    asm volatile(
        "mma.sync.aligned.m16n8k8.row.col.f32.tf32.tf32.f32 "
        "{%0,%1,%2,%3}, {%4,%5,%6,%7}, {%8,%9}, {%0,%1,%2,%3};"
        : "+f"(c[0]), "+f"(c[1]), "+f"(c[2]), "+f"(c[3])
        : "r"(a[0]), "r"(a[1]), "r"(a[2]), "r"(a[3]), "r"(b[0]), "r"(b[1]));
}

// ---------------- complex GEMM via tf32 tensor cores (v2) ----------------
// C = (Ar + iAi)(Br + iBi) + bias.  A: MxK row-major, B: KxN row-major.
// Block tile 64(M) x 128(N), K-step 16, 256 threads = 8 warps (2 warpM x 4 warpN),
// warp tile 32(m) x 32(n) = 2x4 m16n8k8 atoms.
// tf32 conversion (and -Bi negation) done ONCE at smem-fill; inner loop is LDS+MMA only.
// MODE 0: write g_Qr/g_Qi  MODE 1: g_Kr/g_Ki  MODE 2: g_Vr/g_Vi
// MODE 3: A = g_Or/g_Oi, write output (omode 2: interleaved, 1: real only)
#define SA_ST 20    // 20 mod 32: qrow*20+qk covers all 32 banks -> conflict-free
#define SB_ST 136   // 136 mod 32 = 8: qk groups on disjoint bank octets -> conflict-free

template <int MODE>
__global__ void __launch_bounds__(256, 2) cgemm_kernel(
    int M, int K, int N,
    const float* __restrict__ Ap_r, const float* __restrict__ Ap_i,
    const float* __restrict__ Br, const float* __restrict__ Bi,
    const float* __restrict__ bbr, const float* __restrict__ bbi,
    float* __restrict__ outF, int omode)
{
    const float* __restrict__ Ar = (MODE == 3) ? g_Or : Ap_r;
    const float* __restrict__ Ai = (MODE == 3) ? g_Oi : Ap_i;

    __shared__ uint32_t sAr[64 * SA_ST];
    __shared__ uint32_t sAi[64 * SA_ST];
    __shared__ uint32_t sBr[16 * SB_ST];
    __shared__ uint32_t sBi[16 * SB_ST];
    __shared__ uint32_t sBni[16 * SB_ST];

    const int tid = threadIdx.x;
    const int warp = tid >> 5, lane = tid & 31;
    const int qrow = lane >> 2, qk = lane & 3;
    const int warpM = warp >> 2;       // 0..1 -> m offset *32
    const int warpN = warp & 3;        // 0..3 -> n offset *32
    const int m0 = blockIdx.y << 6;
    const int n0 = blockIdx.x << 7;

    float accr[2][4][4] = {};
    float acci[2][4][4] = {};

    const int lm = tid >> 4;       // A-load row (16 rows/pass, 4 passes)
    const int lk = tid & 15;       // A-load k
    const int bn = tid & 127;      // B-load col
    const int bkb = tid >> 7;      // B-load row base (0..1, 8 passes)

    for (int k0 = 0; k0 < K; k0 += 16) {
#pragma unroll
        for (int j = 0; j < 4; j++) {
            int m = lm + j * 16;
            size_t g = (size_t)(m0 + m) * K + (k0 + lk);
            sAr[m * SA_ST + lk] = f2tf32(Ar[g]);
            sAi[m * SA_ST + lk] = f2tf32(Ai[g]);
        }
#pragma unroll
        for (int j = 0; j < 8; j++) {
            int kk = bkb + j * 2;
            size_t g = (size_t)(k0 + kk) * N + (n0 + bn);
            float vr = Br[g], vi = Bi[g];
            sBr[kk * SB_ST + bn]  = f2tf32(vr);
            sBi[kk * SB_ST + bn]  = f2tf32(vi);
            sBni[kk * SB_ST + bn] = f2tf32(-vi);
        }
        __syncthreads();

#pragma unroll
        for (int kc = 0; kc < 16; kc += 8) {
            uint32_t ar[2][4], ai[2][4];
#pragma unroll
            for (int ma = 0; ma < 2; ma++) {
                int mb = warpM * 32 + ma * 16 + qrow;
                ar[ma][0] = sAr[(mb)     * SA_ST + kc + qk];
                ar[ma][1] = sAr[(mb + 8) * SA_ST + kc + qk];
                ar[ma][2] = sAr[(mb)     * SA_ST + kc + qk + 4];
                ar[ma][3] = sAr[(mb + 8) * SA_ST + kc + qk + 4];
                ai[ma][0] = sAi[(mb)     * SA_ST + kc + qk];
                ai[ma][1] = sAi[(mb + 8) * SA_ST + kc + qk];
                ai[ma][2] = sAi[(mb)     * SA_ST + kc + qk + 4];
                ai[ma][3] = sAi[(mb + 8) * SA_ST + kc + qk + 4];
            }
#pragma unroll
            for (int na = 0; na < 4; na++) {
                int nb = warpN * 32 + na * 8 + qrow;
                uint32_t br_[2], bi_[2], bni_[2];
                br_[0]  = sBr[(kc + qk)     * SB_ST + nb];
                br_[1]  = sBr[(kc + qk + 4) * SB_ST + nb];
                bi_[0]  = sBi[(kc + qk)     * SB_ST + nb];
                bi_[1]  = sBi[(kc + qk + 4) * SB_ST + nb];
                bni_[0] = sBni[(kc + qk)     * SB_ST + nb];
                bni_[1] = sBni[(kc + qk + 4) * SB_ST + nb];
#pragma unroll
                for (int ma = 0; ma < 2; ma++) {
                    mma_tf32(accr[ma][na], ar[ma], br_);
                    mma_tf32(accr[ma][na], ai[ma], bni_);
                    mma_tf32(acci[ma][na], ar[ma], bi_);
                    mma_tf32(acci[ma][na], ai[ma], br_);
                }
            }
        }
        __syncthreads();
    }

    // epilogue
#pragma unroll
    for (int ma = 0; ma < 2; ma++) {
#pragma unroll
        for (int na = 0; na < 4; na++) {
#pragma unroll
            for (int c = 0; c < 4; c++) {
                int row = m0 + warpM * 32 + ma * 16 + qrow + ((c >= 2) ? 8 : 0);
                int col = n0 + warpN * 32 + na * 8 + qk * 2 + (c & 1);
                float vr = accr[ma][na][c] + (bbr ? bbr[col] : 0.0f);
                float vi = acci[ma][na][c] + (bbi ? bbi[col] : 0.0f);
                size_t idx = (size_t)row * N + col;
                if (MODE == 0)      { g_Qr[idx] = vr; g_Qi[idx] = vi; }
                else if (MODE == 1) { g_Kr[idx] = vr; g_Ki[idx] = vi; }
                else if (MODE == 2) { g_Vr[idx] = vr; g_Vi[idx] = vi; }
                else {
                    if (omode == 2) { outF[2 * idx] = vr; outF[2 * idx + 1] = vi; }
                    else            { outF[idx] = vr; }
                }
            }
        }
    }
}

// ---------------- attention (online softmax, fp32, vectorized smem) ----------------
#define KT_ 32
#define AST 68

__global__ void __launch_bounds__(256) attn_kernel(const float* __restrict__ mask)
{
    __shared__ __align__(16) float sQr[32 * AST];
    __shared__ __align__(16) float sQi[32 * AST];
    __shared__ __align__(16) float sKr[KT_ * AST];   // reused for Vr
    __shared__ __align__(16) float sKi[KT_ * AST];   // reused for Vi
    __shared__ float sP[32 * 33];
    __shared__ float sM[32], sL[32], sAlpha[32];

    const int tid = threadIdx.x;
    const int warp = tid >> 5, lane = tid & 31;
    const int q0 = blockIdx.x * 32;
    const int b = blockIdx.y >> 4;
    const int h = blockIdx.y & 15;

    for (int i = tid; i < 32 * (HD_ / 4); i += 256) {
        int q = i >> 4;
        int d4 = (i & 15) * 4;
        size_t g = ((size_t)(b * S_ + q0 + q)) * F_ + h * HD_ + d4;
        *(float4*)&sQr[q * AST + d4] = *(const float4*)&g_Qr[g];
        *(float4*)&sQi[q * AST + d4] = *(const float4*)&g_Qi[g];
    }
    if (tid < 32) { sM[tid] = -1e30f; sL[tid] = 0.0f; }

    const int row = tid >> 3;
    const int d0 = (tid & 7) * 8;
    float o_r[8] = {}, o_i[8] = {};

    const float scale = 0.125f;  // 1/sqrt(64)

    for (int kt = 0; kt < LC_ / KT_; kt++) {
        __syncthreads();
        for (int i = tid; i < KT_ * (HD_ / 4); i += 256) {
            int k = i >> 4;
            int d4 = (i & 15) * 4;
            size_t g = ((size_t)(b * LC_ + kt * KT_ + k)) * F_ + h * HD_ + d4;
            *(float4*)&sKr[k * AST + d4] = *(const float4*)&g_Kr[g];
            *(float4*)&sKi[k * AST + d4] = *(const float4*)&g_Ki[g];
        }
        __syncthreads();

        {
            const int r0 = warp * 4;
            float acc[4] = {0.f, 0.f, 0.f, 0.f};
#pragma unroll
            for (int d = 0; d < HD_; d += 4) {
                float4 kr = *(const float4*)&sKr[lane * AST + d];
                float4 ki = *(const float4*)&sKi[lane * AST + d];
#pragma unroll
                for (int r = 0; r < 4; r++) {
                    float4 qr = *(const float4*)&sQr[(r0 + r) * AST + d];
                    float4 qi = *(const float4*)&sQi[(r0 + r) * AST + d];
                    float a = acc[r];
                    a = fmaf(qr.x, kr.x, a); a = fmaf(qr.y, kr.y, a);
                    a = fmaf(qr.z, kr.z, a); a = fmaf(qr.w, kr.w, a);
                    a = fmaf(qi.x, ki.x, a); a = fmaf(qi.y, ki.y, a);
                    a = fmaf(qi.z, ki.z, a); a = fmaf(qi.w, ki.w, a);
                    acc[r] = a;
                }
            }
            float mv = mask ? ((1.0f - mask[b * LC_ + kt * KT_ + lane]) * -1e9f) : 0.0f;
#pragma unroll
            for (int r = 0; r < 4; r++) {
                int q = r0 + r;
                float s = acc[r] * scale + mv;
                float mx = s;
#pragma unroll
                for (int o = 16; o > 0; o >>= 1)
                    mx = fmaxf(mx, __shfl_xor_sync(0xffffffffu, mx, o));
                float m_old = sM[q];
                float m_new = fmaxf(m_old, mx);
                float p = __expf(s - m_new);
                float ps = p;
#pragma unroll
                for (int o = 16; o > 0; o >>= 1)
                    ps += __shfl_xor_sync(0xffffffffu, ps, o);
                sP[q * 33 + lane] = p;
                __syncwarp();
                if (lane == 0) {
                    float alpha = __expf(m_old - m_new);
                    sM[q] = m_new;
                    sL[q] = sL[q] * alpha + ps;
                    sAlpha[q] = alpha;
                }
                __syncwarp();
            }
        }
        __syncthreads();

        for (int i = tid; i < KT_ * (HD_ / 4); i += 256) {
            int k = i >> 4;
            int d4 = (i & 15) * 4;
            size_t g = ((size_t)(b * LC_ + kt * KT_ + k)) * F_ + h * HD_ + d4;
            *(float4*)&sKr[k * AST + d4] = *(const float4*)&g_Vr[g];
            *(float4*)&sKi[k * AST + d4] = *(const float4*)&g_Vi[g];
        }
        __syncthreads();

        float alpha = sAlpha[row];
#pragma unroll
        for (int j = 0; j < 8; j++) { o_r[j] *= alpha; o_i[j] *= alpha; }
#pragma unroll 4
        for (int k = 0; k < KT_; k++) {
            float p = sP[row * 33 + k];
            float4 vr0 = *(const float4*)&sKr[k * AST + d0];
            float4 vr1 = *(const float4*)&sKr[k * AST + d0 + 4];
            float4 vi0 = *(const float4*)&sKi[k * AST + d0];
            float4 vi1 = *(const float4*)&sKi[k * AST + d0 + 4];
            o_r[0] = fmaf(p, vr0.x, o_r[0]); o_r[1] = fmaf(p, vr0.y, o_r[1]);
            o_r[2] = fmaf(p, vr0.z, o_r[2]); o_r[3] = fmaf(p, vr0.w, o_r[3]);
            o_r[4] = fmaf(p, vr1.x, o_r[4]); o_r[5] = fmaf(p, vr1.y, o_r[5]);
            o_r[6] = fmaf(p, vr1.z, o_r[6]); o_r[7] = fmaf(p, vr1.w, o_r[7]);
            o_i[0] = fmaf(p, vi0.x, o_i[0]); o_i[1] = fmaf(p, vi0.y, o_i[1]);
            o_i[2] = fmaf(p, vi0.z, o_i[2]); o_i[3] = fmaf(p, vi0.w, o_i[3]);
            o_i[4] = fmaf(p, vi1.x, o_i[4]); o_i[5] = fmaf(p, vi1.y, o_i[5]);
            o_i[6] = fmaf(p, vi1.z, o_i[6]); o_i[7] = fmaf(p, vi1.w, o_i[7]);
        }
    }
    __syncthreads();

    float inv = 1.0f / sL[row];
    size_t g = ((size_t)(b * S_ + q0 + row)) * F_ + h * HD_ + d0;
#pragma unroll
    for (int j = 0; j < 8; j++) {
        g_Or[g + j] = o_r[j] * inv;
        g_Oi[g + j] = o_i[j] * inv;
    }
}

// Fallback: bounded zero-fill so graph capture always has nodes.
__global__ void fill_zero_kernel(float* p, long long n)
{
    long long i = (long long)blockIdx.x * blockDim.x + threadIdx.x;
    if (i < n) p[i] = 0.0f;
}

// ---------------- launch ----------------
extern "C" void kernel_launch(void* const* d_in, const int* in_sizes, int n_in,
                              void* d_out, int out_size)
{
    const long long MN = (long long)B_ * S_ * F_;   // 4,194,304 complex outputs

    const float* x4M[2]  = {0, 0}; int n4M = 0;   // x_r, x_i        (4194304)
    const float* xctx[2] = {0, 0}; int nctx = 0;  // ctx_r, ctx_i    (1572864)
    const float* pmask   = 0;                     // mask            (2048)
    const float* wF[4]   = {0, 0, 0, 0}; int nwF = 0;  // Wqr,Wqi,Wor,Woi (1048576)
    const float* wC[4]   = {0, 0, 0, 0}; int nwC = 0;  // Wkr,Wki,Wvr,Wvi (786432)
    const float* bias[8] = {0, 0, 0, 0, 0, 0, 0, 0}; int nb = 0;  // 8 x (1024)

    for (int i = 0; i < n_in; i++) {
        const float* p = (const float*)d_in[i];
        long long sz = in_sizes[i];
        if (sz == (long long)B_ * S_ * F_)        { if (n4M < 2) x4M[n4M++] = p; }
        else if (sz == (long long)B_ * LC_ * DC_) { if (nctx < 2) xctx[nctx++] = p; }
        else if (sz == (long long)B_ * LC_)       { pmask = p; }
        else if (sz == (long long)F_ * F_)        { if (nwF < 4) wF[nwF++] = p; }
        else if (sz == (long long)DC_ * F_)       { if (nwC < 4) wC[nwC++] = p; }
        else if (sz == (long long)F_)             { if (nb < 8) bias[nb++] = p; }
    }

    const float* x_r = x4M[0],  *x_i = x4M[1];
    const float* ctx_r = xctx[0], *ctx_i = xctx[1];
    const float* Wqr = wF[0], *Wqi = wF[1], *Wor = wF[2], *Woi = wF[3];
    const float* Wkr = wC[0], *Wki = wC[1], *Wvr = wC[2], *Wvi = wC[3];
    const float* bqr = bias[0], *bqi = bias[1];
    const float* bkr = bias[2], *bki = bias[3];
    const float* bvr = bias[4], *bvi = bias[5];
    const float* bor = bias[6], *boi = bias[7];

    int omode = ((long long)out_size >= 2 * MN) ? 2 : 1;

    if (!x_r || !x_i || !ctx_r || !ctx_i || !Wqr || !Wqi || !Wor || !Woi ||
        !Wkr || !Wki || !Wvr || !Wvi) {
        long long n = (omode == 2) ? 2 * MN : MN;
        fill_zero_kernel<<<(unsigned)((n + 255) / 256), 256>>>((float*)d_out, n);
        return;
    }

    dim3 blk(256);

    // Q = x @ Wq   (4096 x 1024 -> 1024)
    cgemm_kernel<0><<<dim3(F_ / 128, (B_ * S_) / 64), blk>>>(
        B_ * S_, F_, F_, x_r, x_i, Wqr, Wqi, bqr, bqi, nullptr, 0);
    // K = ctx @ Wk (2048 x 768 -> 1024)
    cgemm_kernel<1><<<dim3(F_ / 128, (B_ * LC_) / 64), blk>>>(
        B_ * LC_, DC_, F_, ctx_r, ctx_i, Wkr, Wki, bkr, bki, nullptr, 0);
    // V = ctx @ Wv
    cgemm_kernel<2><<<dim3(F_ / 128, (B_ * LC_) / 64), blk>>>(
        B_ * LC_, DC_, F_, ctx_r, ctx_i, Wvr, Wvi, bvr, bvi, nullptr, 0);

    // attention (reads g_Q*, g_K*, g_V*; writes g_O*)
    attn_kernel<<<dim3(S_ / 32, B_ * H_), blk>>>(pmask);

    // y = O @ Wo -> output (adaptive layout)
    cgemm_kernel<3><<<dim3(F_ / 128, (B_ * S_) / 64), blk>>>(
        B_ * S_, F_, F_, nullptr, nullptr, Wor, Woi, bor, boi, (float*)d_out, omode);
}

// round 9
// speedup vs baseline: 1.9140x; 1.3785x over previous
#include <cuda_runtime.h>
#include <math.h>
#include <stdint.h>

#define B_   2
#define S_   2048
#define LC_  1024
#define F_   1024
#define DC_  768
#define H_   16
#define HD_  64

// ---------------- scratch (no allocation allowed; zero-initialized) ----------------
__device__ __align__(16) float g_Qr[(size_t)B_ * S_ * F_];
__device__ __align__(16) float g_Qi[(size_t)B_ * S_ * F_];
__device__ __align__(16) float g_Kr[(size_t)B_ * LC_ * F_];
__device__ __align__(16) float g_Ki[(size_t)B_ * LC_ * F_];
__device__ __align__(16) float g_Vr[(size_t)B_ * LC_ * F_];
__device__ __align__(16) float g_Vi[(size_t)B_ * LC_ * F_];
__device__ __align__(16) float g_Or[(size_t)B_ * S_ * F_];
__device__ __align__(16) float g_Oi[(size_t)B_ * S_ * F_];

// ---------------- tf32 mma helpers ----------------
__device__ __forceinline__ uint32_t f2tf32(float x) {
    uint32_t r;
    asm("cvt.rna.tf32.f32 %0, %1;" : "=r"(r) : "f"(x));
    return r;
}

__device__ __forceinline__ void mma_tf32(float c[4], const uint32_t a[4], const uint32_t b[2]) {
    asm volatile(
        "mma.sync.aligned.m16n8k8.row.col.f32.tf32.tf32.f32 "
        "{%0,%1,%2,%3}, {%4,%5,%6,%7}, {%8,%9}, {%0,%1,%2,%3};"
        : "+f"(c[0]), "+f"(c[1]), "+f"(c[2]), "+f"(c[3])
        : "r"(a[0]), "r"(a[1]), "r"(a[2]), "r"(a[3]), "r"(b[0]), "r"(b[1]));
}

// ---------------- complex GEMM via tf32 tensor cores (unchanged from R8) ----------------
#define SA_ST 20
#define SB_ST 136

template <int MODE>
__global__ void __launch_bounds__(256, 2) cgemm_kernel(
    int M, int K, int N,
    const float* __restrict__ Ap_r, const float* __restrict__ Ap_i,
    const float* __restrict__ Br, const float* __restrict__ Bi,
    const float* __restrict__ bbr, const float* __restrict__ bbi,
    float* __restrict__ outF, int omode)
{
    const float* __restrict__ Ar = (MODE == 3) ? g_Or : Ap_r;
    const float* __restrict__ Ai = (MODE == 3) ? g_Oi : Ap_i;

    __shared__ uint32_t sAr[64 * SA_ST];
    __shared__ uint32_t sAi[64 * SA_ST];
    __shared__ uint32_t sBr[16 * SB_ST];
    __shared__ uint32_t sBi[16 * SB_ST];
    __shared__ uint32_t sBni[16 * SB_ST];

    const int tid = threadIdx.x;
    const int warp = tid >> 5, lane = tid & 31;
    const int qrow = lane >> 2, qk = lane & 3;
    const int warpM = warp >> 2;
    const int warpN = warp & 3;
    const int m0 = blockIdx.y << 6;
    const int n0 = blockIdx.x << 7;

    float accr[2][4][4] = {};
    float acci[2][4][4] = {};

    const int lm = tid >> 4;
    const int lk = tid & 15;
    const int bn = tid & 127;
    const int bkb = tid >> 7;

    for (int k0 = 0; k0 < K; k0 += 16) {
#pragma unroll
        for (int j = 0; j < 4; j++) {
            int m = lm + j * 16;
            size_t g = (size_t)(m0 + m) * K + (k0 + lk);
            sAr[m * SA_ST + lk] = f2tf32(Ar[g]);
            sAi[m * SA_ST + lk] = f2tf32(Ai[g]);
        }
#pragma unroll
        for (int j = 0; j < 8; j++) {
            int kk = bkb + j * 2;
            size_t g = (size_t)(k0 + kk) * N + (n0 + bn);
            float vr = Br[g], vi = Bi[g];
            sBr[kk * SB_ST + bn]  = f2tf32(vr);
            sBi[kk * SB_ST + bn]  = f2tf32(vi);
            sBni[kk * SB_ST + bn] = f2tf32(-vi);
        }
        __syncthreads();

#pragma unroll
        for (int kc = 0; kc < 16; kc += 8) {
            uint32_t ar[2][4], ai[2][4];
#pragma unroll
            for (int ma = 0; ma < 2; ma++) {
                int mb = warpM * 32 + ma * 16 + qrow;
                ar[ma][0] = sAr[(mb)     * SA_ST + kc + qk];
                ar[ma][1] = sAr[(mb + 8) * SA_ST + kc + qk];
                ar[ma][2] = sAr[(mb)     * SA_ST + kc + qk + 4];
                ar[ma][3] = sAr[(mb + 8) * SA_ST + kc + qk + 4];
                ai[ma][0] = sAi[(mb)     * SA_ST + kc + qk];
                ai[ma][1] = sAi[(mb + 8) * SA_ST + kc + qk];
                ai[ma][2] = sAi[(mb)     * SA_ST + kc + qk + 4];
                ai[ma][3] = sAi[(mb + 8) * SA_ST + kc + qk + 4];
            }
#pragma unroll
            for (int na = 0; na < 4; na++) {
                int nb = warpN * 32 + na * 8 + qrow;
                uint32_t br_[2], bi_[2], bni_[2];
                br_[0]  = sBr[(kc + qk)     * SB_ST + nb];
                br_[1]  = sBr[(kc + qk + 4) * SB_ST + nb];
                bi_[0]  = sBi[(kc + qk)     * SB_ST + nb];
                bi_[1]  = sBi[(kc + qk + 4) * SB_ST + nb];
                bni_[0] = sBni[(kc + qk)     * SB_ST + nb];
                bni_[1] = sBni[(kc + qk + 4) * SB_ST + nb];
#pragma unroll
                for (int ma = 0; ma < 2; ma++) {
                    mma_tf32(accr[ma][na], ar[ma], br_);
                    mma_tf32(accr[ma][na], ai[ma], bni_);
                    mma_tf32(acci[ma][na], ar[ma], bi_);
                    mma_tf32(acci[ma][na], ai[ma], br_);
                }
            }
        }
        __syncthreads();
    }

#pragma unroll
    for (int ma = 0; ma < 2; ma++) {
#pragma unroll
        for (int na = 0; na < 4; na++) {
#pragma unroll
            for (int c = 0; c < 4; c++) {
                int row = m0 + warpM * 32 + ma * 16 + qrow + ((c >= 2) ? 8 : 0);
                int col = n0 + warpN * 32 + na * 8 + qk * 2 + (c & 1);
                float vr = accr[ma][na][c] + (bbr ? bbr[col] : 0.0f);
                float vi = acci[ma][na][c] + (bbi ? bbi[col] : 0.0f);
                size_t idx = (size_t)row * N + col;
                if (MODE == 0)      { g_Qr[idx] = vr; g_Qi[idx] = vi; }
                else if (MODE == 1) { g_Kr[idx] = vr; g_Ki[idx] = vi; }
                else if (MODE == 2) { g_Vr[idx] = vr; g_Vi[idx] = vi; }
                else {
                    if (omode == 2) { outF[2 * idx] = vr; outF[2 * idx + 1] = vi; }
                    else            { outF[idx] = vr; }
                }
            }
        }
    }
}

// ---------------- attention (online softmax; broadcast-friendly PV) ----------------
// Block = (b, h, 32 q-rows), 256 threads, k-tiles of 32.
// PV mapping: dc = warp (d-chunk of 8), rg = 4-row group, ksub = 2-bit k split.
// All lanes of a warp share dc -> V loads have only 4 distinct addresses/warp
// (8-lane broadcast) -> crossbar traffic for V ~= tile size.
#define KT_ 32
#define AST 68

__global__ void __launch_bounds__(256) attn_kernel(const float* __restrict__ mask)
{
    __shared__ __align__(16) float sQr[32 * AST];
    __shared__ __align__(16) float sQi[32 * AST];
    __shared__ __align__(16) float sKr[KT_ * AST];   // reused for Vr
    __shared__ __align__(16) float sKi[KT_ * AST];   // reused for Vi
    __shared__ float sP[32 * 33];
    __shared__ float sM[32], sL[32], sAlpha[32];

    const int tid = threadIdx.x;
    const int warp = tid >> 5, lane = tid & 31;
    const int q0 = blockIdx.x * 32;
    const int b = blockIdx.y >> 4;
    const int h = blockIdx.y & 15;

    for (int i = tid; i < 32 * (HD_ / 4); i += 256) {
        int q = i >> 4;
        int d4 = (i & 15) * 4;
        size_t g = ((size_t)(b * S_ + q0 + q)) * F_ + h * HD_ + d4;
        *(float4*)&sQr[q * AST + d4] = *(const float4*)&g_Qr[g];
        *(float4*)&sQi[q * AST + d4] = *(const float4*)&g_Qi[g];
    }
    if (tid < 32) { sM[tid] = -1e30f; sL[tid] = 0.0f; }

    // PV decomposition: tid = dc(3b) | rg(3b) | ksub(2b)
    const int ksub = tid & 3;
    const int rg   = (tid >> 2) & 7;
    const int dc   = tid >> 5;           // == warp
    const int d0   = dc * 8;
    float o_r[4][8] = {};
    float o_i[4][8] = {};

    const float scale = 0.125f;  // 1/sqrt(64)

    for (int kt = 0; kt < LC_ / KT_; kt++) {
        __syncthreads();
        for (int i = tid; i < KT_ * (HD_ / 4); i += 256) {
            int k = i >> 4;
            int d4 = (i & 15) * 4;
            size_t g = ((size_t)(b * LC_ + kt * KT_ + k)) * F_ + h * HD_ + d4;
            *(float4*)&sKr[k * AST + d4] = *(const float4*)&g_Kr[g];
            *(float4*)&sKi[k * AST + d4] = *(const float4*)&g_Ki[g];
        }
        __syncthreads();

        // QK scores: warp -> 4 rows, lane -> key
        {
            const int r0 = warp * 4;
            float acc[4] = {0.f, 0.f, 0.f, 0.f};
#pragma unroll
            for (int d = 0; d < HD_; d += 4) {
                float4 kr = *(const float4*)&sKr[lane * AST + d];
                float4 ki = *(const float4*)&sKi[lane * AST + d];
#pragma unroll
                for (int r = 0; r < 4; r++) {
                    float4 qr = *(const float4*)&sQr[(r0 + r) * AST + d];
                    float4 qi = *(const float4*)&sQi[(r0 + r) * AST + d];
                    float a = acc[r];
                    a = fmaf(qr.x, kr.x, a); a = fmaf(qr.y, kr.y, a);
                    a = fmaf(qr.z, kr.z, a); a = fmaf(qr.w, kr.w, a);
                    a = fmaf(qi.x, ki.x, a); a = fmaf(qi.y, ki.y, a);
                    a = fmaf(qi.z, ki.z, a); a = fmaf(qi.w, ki.w, a);
                    acc[r] = a;
                }
            }
            float mv = mask ? ((1.0f - mask[b * LC_ + kt * KT_ + lane]) * -1e9f) : 0.0f;
#pragma unroll
            for (int r = 0; r < 4; r++) {
                int q = r0 + r;
                float s = acc[r] * scale + mv;
                float mx = s;
#pragma unroll
                for (int o = 16; o > 0; o >>= 1)
                    mx = fmaxf(mx, __shfl_xor_sync(0xffffffffu, mx, o));
                float m_old = sM[q];
                float m_new = fmaxf(m_old, mx);
                float p = __expf(s - m_new);
                float ps = p;
#pragma unroll
                for (int o = 16; o > 0; o >>= 1)
                    ps += __shfl_xor_sync(0xffffffffu, ps, o);
                sP[q * 33 + lane] = p;
                __syncwarp();
                if (lane == 0) {
                    float alpha = __expf(m_old - m_new);
                    sM[q] = m_new;
                    sL[q] = sL[q] * alpha + ps;
                    sAlpha[q] = alpha;
                }
                __syncwarp();
            }
        }
        __syncthreads();

        // load V tile into K buffers
        for (int i = tid; i < KT_ * (HD_ / 4); i += 256) {
            int k = i >> 4;
            int d4 = (i & 15) * 4;
            size_t g = ((size_t)(b * LC_ + kt * KT_ + k)) * F_ + h * HD_ + d4;
            *(float4*)&sKr[k * AST + d4] = *(const float4*)&g_Vr[g];
            *(float4*)&sKi[k * AST + d4] = *(const float4*)&g_Vi[g];
        }
        __syncthreads();

        // PV: thread owns 4 rows (rg*4..+3) x 8 d (d0..d0+7), k-split by ksub
        float al[4];
#pragma unroll
        for (int r = 0; r < 4; r++) al[r] = sAlpha[rg * 4 + r];
#pragma unroll
        for (int r = 0; r < 4; r++)
#pragma unroll
            for (int j = 0; j < 8; j++) { o_r[r][j] *= al[r]; o_i[r][j] *= al[r]; }

#pragma unroll
        for (int j = 0; j < 8; j++) {
            int k = ksub + 4 * j;
            float4 vr0 = *(const float4*)&sKr[k * AST + d0];
            float4 vr1 = *(const float4*)&sKr[k * AST + d0 + 4];
            float4 vi0 = *(const float4*)&sKi[k * AST + d0];
            float4 vi1 = *(const float4*)&sKi[k * AST + d0 + 4];
            float p[4];
#pragma unroll
            for (int r = 0; r < 4; r++) p[r] = sP[(rg * 4 + r) * 33 + k];
#pragma unroll
            for (int r = 0; r < 4; r++) {
                o_r[r][0] = fmaf(p[r], vr0.x, o_r[r][0]);
                o_r[r][1] = fmaf(p[r], vr0.y, o_r[r][1]);
                o_r[r][2] = fmaf(p[r], vr0.z, o_r[r][2]);
                o_r[r][3] = fmaf(p[r], vr0.w, o_r[r][3]);
                o_r[r][4] = fmaf(p[r], vr1.x, o_r[r][4]);
                o_r[r][5] = fmaf(p[r], vr1.y, o_r[r][5]);
                o_r[r][6] = fmaf(p[r], vr1.z, o_r[r][6]);
                o_r[r][7] = fmaf(p[r], vr1.w, o_r[r][7]);
                o_i[r][0] = fmaf(p[r], vi0.x, o_i[r][0]);
                o_i[r][1] = fmaf(p[r], vi0.y, o_i[r][1]);
                o_i[r][2] = fmaf(p[r], vi0.z, o_i[r][2]);
                o_i[r][3] = fmaf(p[r], vi0.w, o_i[r][3]);
                o_i[r][4] = fmaf(p[r], vi1.x, o_i[r][4]);
                o_i[r][5] = fmaf(p[r], vi1.y, o_i[r][5]);
                o_i[r][6] = fmaf(p[r], vi1.z, o_i[r][6]);
                o_i[r][7] = fmaf(p[r], vi1.w, o_i[r][7]);
            }
        }
    }
    __syncthreads();

    // k-split butterfly reduction across ksub (low 2 lane bits)
#pragma unroll
    for (int r = 0; r < 4; r++) {
#pragma unroll
        for (int j = 0; j < 8; j++) {
            float vr = o_r[r][j], vi = o_i[r][j];
            vr += __shfl_xor_sync(0xffffffffu, vr, 1);
            vi += __shfl_xor_sync(0xffffffffu, vi, 1);
            vr += __shfl_xor_sync(0xffffffffu, vr, 2);
            vi += __shfl_xor_sync(0xffffffffu, vi, 2);
            o_r[r][j] = vr; o_i[r][j] = vi;
        }
    }

    // each ksub writes its 2 d-values per row
#pragma unroll
    for (int r = 0; r < 4; r++) {
        int row = rg * 4 + r;
        float inv = 1.0f / sL[row];
        size_t g = ((size_t)(b * S_ + q0 + row)) * F_ + h * HD_ + d0;
#pragma unroll
        for (int t = 0; t < 2; t++) {
            int j = ksub * 2 + t;
            g_Or[g + j] = o_r[r][j] * inv;
            g_Oi[g + j] = o_i[r][j] * inv;
        }
    }
}

// Fallback: bounded zero-fill so graph capture always has nodes.
__global__ void fill_zero_kernel(float* p, long long n)
{
    long long i = (long long)blockIdx.x * blockDim.x + threadIdx.x;
    if (i < n) p[i] = 0.0f;
}

// ---------------- launch ----------------
extern "C" void kernel_launch(void* const* d_in, const int* in_sizes, int n_in,
                              void* d_out, int out_size)
{
    const long long MN = (long long)B_ * S_ * F_;

    const float* x4M[2]  = {0, 0}; int n4M = 0;
    const float* xctx[2] = {0, 0}; int nctx = 0;
    const float* pmask   = 0;
    const float* wF[4]   = {0, 0, 0, 0}; int nwF = 0;
    const float* wC[4]   = {0, 0, 0, 0}; int nwC = 0;
    const float* bias[8] = {0, 0, 0, 0, 0, 0, 0, 0}; int nb = 0;

    for (int i = 0; i < n_in; i++) {
        const float* p = (const float*)d_in[i];
        long long sz = in_sizes[i];
        if (sz == (long long)B_ * S_ * F_)        { if (n4M < 2) x4M[n4M++] = p; }
        else if (sz == (long long)B_ * LC_ * DC_) { if (nctx < 2) xctx[nctx++] = p; }
        else if (sz == (long long)B_ * LC_)       { pmask = p; }
        else if (sz == (long long)F_ * F_)        { if (nwF < 4) wF[nwF++] = p; }
        else if (sz == (long long)DC_ * F_)       { if (nwC < 4) wC[nwC++] = p; }
        else if (sz == (long long)F_)             { if (nb < 8) bias[nb++] = p; }
    }

    const float* x_r = x4M[0],  *x_i = x4M[1];
    const float* ctx_r = xctx[0], *ctx_i = xctx[1];
    const float* Wqr = wF[0], *Wqi = wF[1], *Wor = wF[2], *Woi = wF[3];
    const float* Wkr = wC[0], *Wki = wC[1], *Wvr = wC[2], *Wvi = wC[3];
    const float* bqr = bias[0], *bqi = bias[1];
    const float* bkr = bias[2], *bki = bias[3];
    const float* bvr = bias[4], *bvi = bias[5];
    const float* bor = bias[6], *boi = bias[7];

    int omode = ((long long)out_size >= 2 * MN) ? 2 : 1;

    if (!x_r || !x_i || !ctx_r || !ctx_i || !Wqr || !Wqi || !Wor || !Woi ||
        !Wkr || !Wki || !Wvr || !Wvi) {
        long long n = (omode == 2) ? 2 * MN : MN;
        fill_zero_kernel<<<(unsigned)((n + 255) / 256), 256>>>((float*)d_out, n);
        return;
    }

    dim3 blk(256);

    cgemm_kernel<0><<<dim3(F_ / 128, (B_ * S_) / 64), blk>>>(
        B_ * S_, F_, F_, x_r, x_i, Wqr, Wqi, bqr, bqi, nullptr, 0);
    cgemm_kernel<1><<<dim3(F_ / 128, (B_ * LC_) / 64), blk>>>(
        B_ * LC_, DC_, F_, ctx_r, ctx_i, Wkr, Wki, bkr, bki, nullptr, 0);
    cgemm_kernel<2><<<dim3(F_ / 128, (B_ * LC_) / 64), blk>>>(
        B_ * LC_, DC_, F_, ctx_r, ctx_i, Wvr, Wvi, bvr, bvi, nullptr, 0);

    attn_kernel<<<dim3(S_ / 32, B_ * H_), blk>>>(pmask);

    cgemm_kernel<3><<<dim3(F_ / 128, (B_ * S_) / 64), blk>>>(
        B_ * S_, F_, F_, nullptr, nullptr, Wor, Woi, bor, boi, (float*)d_out, omode);
}

// round 11
// speedup vs baseline: 2.0729x; 1.0830x over previous
#include <cuda_runtime.h>
#include <math.h>
#include <stdint.h>

#define B_   2
#define S_   2048
#define LC_  1024
#define F_   1024
#define DC_  768
#define H_   16
#define HD_  64

// ---------------- scratch (no allocation allowed; zero-initialized) ----------------
__device__ __align__(16) float g_Qr[(size_t)B_ * S_ * F_];
__device__ __align__(16) float g_Qi[(size_t)B_ * S_ * F_];
__device__ __align__(16) float g_Kr[(size_t)B_ * LC_ * F_];
__device__ __align__(16) float g_Ki[(size_t)B_ * LC_ * F_];
__device__ __align__(16) float g_Vr[(size_t)B_ * LC_ * F_];
__device__ __align__(16) float g_Vi[(size_t)B_ * LC_ * F_];
__device__ __align__(16) float g_Or[(size_t)B_ * S_ * F_];
__device__ __align__(16) float g_Oi[(size_t)B_ * S_ * F_];

// ---------------- tf32 mma helpers ----------------
__device__ __forceinline__ uint32_t f2tf32(float x) {
    uint32_t r;
    asm("cvt.rna.tf32.f32 %0, %1;" : "=r"(r) : "f"(x));
    return r;
}

__device__ __forceinline__ void mma_tf32(float c[4], const uint32_t a[4], const uint32_t b[2]) {
    asm volatile(
        "mma.sync.aligned.m16n8k8.row.col.f32.tf32.tf32.f32 "
        "{%0,%1,%2,%3}, {%4,%5,%6,%7}, {%8,%9}, {%0,%1,%2,%3};"
        : "+f"(c[0]), "+f"(c[1]), "+f"(c[2]), "+f"(c[3])
        : "r"(a[0]), "r"(a[1]), "r"(a[2]), "r"(a[3]), "r"(b[0]), "r"(b[1]));
}

// ---------------- complex GEMM via tf32 tensor cores (unchanged from R8) ----------------
#define SA_ST 20
#define SB_ST 136

template <int MODE>
__global__ void __launch_bounds__(256, 2) cgemm_kernel(
    int M, int K, int N,
    const float* __restrict__ Ap_r, const float* __restrict__ Ap_i,
    const float* __restrict__ Br, const float* __restrict__ Bi,
    const float* __restrict__ bbr, const float* __restrict__ bbi,
    float* __restrict__ outF, int omode)
{
    const float* __restrict__ Ar = (MODE == 3) ? g_Or : Ap_r;
    const float* __restrict__ Ai = (MODE == 3) ? g_Oi : Ap_i;

    __shared__ uint32_t sAr[64 * SA_ST];
    __shared__ uint32_t sAi[64 * SA_ST];
    __shared__ uint32_t sBr[16 * SB_ST];
    __shared__ uint32_t sBi[16 * SB_ST];
    __shared__ uint32_t sBni[16 * SB_ST];

    const int tid = threadIdx.x;
    const int warp = tid >> 5, lane = tid & 31;
    const int qrow = lane >> 2, qk = lane & 3;
    const int warpM = warp >> 2;
    const int warpN = warp & 3;
    const int m0 = blockIdx.y << 6;
    const int n0 = blockIdx.x << 7;

    float accr[2][4][4] = {};
    float acci[2][4][4] = {};

    const int lm = tid >> 4;
    const int lk = tid & 15;
    const int bn = tid & 127;
    const int bkb = tid >> 7;

    for (int k0 = 0; k0 < K; k0 += 16) {
#pragma unroll
        for (int j = 0; j < 4; j++) {
            int m = lm + j * 16;
            size_t g = (size_t)(m0 + m) * K + (k0 + lk);
            sAr[m * SA_ST + lk] = f2tf32(Ar[g]);
            sAi[m * SA_ST + lk] = f2tf32(Ai[g]);
        }
#pragma unroll
        for (int j = 0; j < 8; j++) {
            int kk = bkb + j * 2;
            size_t g = (size_t)(k0 + kk) * N + (n0 + bn);
            float vr = Br[g], vi = Bi[g];
            sBr[kk * SB_ST + bn]  = f2tf32(vr);
            sBi[kk * SB_ST + bn]  = f2tf32(vi);
            sBni[kk * SB_ST + bn] = f2tf32(-vi);
        }
        __syncthreads();

#pragma unroll
        for (int kc = 0; kc < 16; kc += 8) {
            uint32_t ar[2][4], ai[2][4];
#pragma unroll
            for (int ma = 0; ma < 2; ma++) {
                int mb = warpM * 32 + ma * 16 + qrow;
                ar[ma][0] = sAr[(mb)     * SA_ST + kc + qk];
                ar[ma][1] = sAr[(mb + 8) * SA_ST + kc + qk];
                ar[ma][2] = sAr[(mb)     * SA_ST + kc + qk + 4];
                ar[ma][3] = sAr[(mb + 8) * SA_ST + kc + qk + 4];
                ai[ma][0] = sAi[(mb)     * SA_ST + kc + qk];
                ai[ma][1] = sAi[(mb + 8) * SA_ST + kc + qk];
                ai[ma][2] = sAi[(mb)     * SA_ST + kc + qk + 4];
                ai[ma][3] = sAi[(mb + 8) * SA_ST + kc + qk + 4];
            }
#pragma unroll
            for (int na = 0; na < 4; na++) {
                int nb = warpN * 32 + na * 8 + qrow;
                uint32_t br_[2], bi_[2], bni_[2];
                br_[0]  = sBr[(kc + qk)     * SB_ST + nb];
                br_[1]  = sBr[(kc + qk + 4) * SB_ST + nb];
                bi_[0]  = sBi[(kc + qk)     * SB_ST + nb];
                bi_[1]  = sBi[(kc + qk + 4) * SB_ST + nb];
                bni_[0] = sBni[(kc + qk)     * SB_ST + nb];
                bni_[1] = sBni[(kc + qk + 4) * SB_ST + nb];
#pragma unroll
                for (int ma = 0; ma < 2; ma++) {
                    mma_tf32(accr[ma][na], ar[ma], br_);
                    mma_tf32(accr[ma][na], ai[ma], bni_);
                    mma_tf32(acci[ma][na], ar[ma], bi_);
                    mma_tf32(acci[ma][na], ai[ma], br_);
                }
            }
        }
        __syncthreads();
    }

#pragma unroll
    for (int ma = 0; ma < 2; ma++) {
#pragma unroll
        for (int na = 0; na < 4; na++) {
#pragma unroll
            for (int c = 0; c < 4; c++) {
                int row = m0 + warpM * 32 + ma * 16 + qrow + ((c >= 2) ? 8 : 0);
                int col = n0 + warpN * 32 + na * 8 + qk * 2 + (c & 1);
                float vr = accr[ma][na][c] + (bbr ? bbr[col] : 0.0f);
                float vi = acci[ma][na][c] + (bbi ? bbi[col] : 0.0f);
                size_t idx = (size_t)row * N + col;
                if (MODE == 0)      { g_Qr[idx] = vr; g_Qi[idx] = vi; }
                else if (MODE == 1) { g_Kr[idx] = vr; g_Ki[idx] = vi; }
                else if (MODE == 2) { g_Vr[idx] = vr; g_Vi[idx] = vi; }
                else {
                    if (omode == 2) { outF[2 * idx] = vr; outF[2 * idx + 1] = vi; }
                    else            { outF[idx] = vr; }
                }
            }
        }
    }
}

// ---------------- attention: tf32-mma QK (Q split hi/lo) + online softmax + broadcast PV ----
// Block = (b, h, 32 q-rows), 256 threads = 8 warps, k-tiles of 32.
// QK: scores 32x32 = 8 m16n8 warp atoms; K-dim = 128 (64 d x {r,i}), 8 k-steps.
//     Q is split hi+lo tf32 (once per block) so only K-side tf32 rounding remains.
// Softmax: warp -> 4 rows, lane -> key (reads raw scores from sP).
// PV: fp32, broadcast-friendly mapping (dc=warp, rg, ksub) from R9.
#define AST 68
#define ATTN_SMEM_BYTES ((6 * 32 * AST + 32 * 33 + 96) * 4)

__global__ void __launch_bounds__(256) attn_kernel(const float* __restrict__ mask)
{
    extern __shared__ __align__(16) float sm[];
    float* sQhr = sm;                    // Q hi, real   32*AST
    float* sQhi_ = sQhr + 32 * AST;      // Q hi, imag
    float* sQlr = sQhi_ + 32 * AST;      // Q lo, real
    float* sQli = sQlr + 32 * AST;       // Q lo, imag
    float* sKr  = sQli + 32 * AST;       // K tf32 / V fp32, real
    float* sKi  = sKr + 32 * AST;        // K tf32 / V fp32, imag
    float* sP   = sKi + 32 * AST;        // scores -> probs, 32*33
    float* sM   = sP + 32 * 33;
    float* sL   = sM + 32;
    float* sAlpha = sL + 32;

    const int tid = threadIdx.x;
    const int warp = tid >> 5, lane = tid & 31;
    const int qrow = lane >> 2, qk = lane & 3;
    const int q0 = blockIdx.x * 32;
    const int b = blockIdx.y >> 4;
    const int h = blockIdx.y & 15;

    // ---- load Q tile, split into tf32 hi + lo ----
    for (int i = tid; i < 32 * (HD_ / 4); i += 256) {
        int q = i >> 4;
        int d4 = (i & 15) * 4;
        size_t g = ((size_t)(b * S_ + q0 + q)) * F_ + h * HD_ + d4;
        float4 vr = *(const float4*)&g_Qr[g];
        float4 vi = *(const float4*)&g_Qi[g];
        float4 hr, lr, hi2, li;
        hr.x = __uint_as_float(f2tf32(vr.x)); lr.x = __uint_as_float(f2tf32(vr.x - hr.x));
        hr.y = __uint_as_float(f2tf32(vr.y)); lr.y = __uint_as_float(f2tf32(vr.y - hr.y));
        hr.z = __uint_as_float(f2tf32(vr.z)); lr.z = __uint_as_float(f2tf32(vr.z - hr.z));
        hr.w = __uint_as_float(f2tf32(vr.w)); lr.w = __uint_as_float(f2tf32(vr.w - hr.w));
        hi2.x = __uint_as_float(f2tf32(vi.x)); li.x = __uint_as_float(f2tf32(vi.x - hi2.x));
        hi2.y = __uint_as_float(f2tf32(vi.y)); li.y = __uint_as_float(f2tf32(vi.y - hi2.y));
        hi2.z = __uint_as_float(f2tf32(vi.z)); li.z = __uint_as_float(f2tf32(vi.z - hi2.z));
        hi2.w = __uint_as_float(f2tf32(vi.w)); li.w = __uint_as_float(f2tf32(vi.w - hi2.w));
        *(float4*)&sQhr[q * AST + d4] = hr;
        *(float4*)&sQlr[q * AST + d4] = lr;
        *(float4*)&sQhi_[q * AST + d4] = hi2;
        *(float4*)&sQli[q * AST + d4] = li;
    }
    if (tid < 32) { sM[tid] = -1e30f; sL[tid] = 0.0f; }

    // PV decomposition (R9): tid = dc(3b) | rg(3b) | ksub(2b)
    const int ksub = tid & 3;
    const int rg   = (tid >> 2) & 7;
    const int dc   = tid >> 5;
    const int d0   = dc * 8;
    float o_r[4][8] = {};
    float o_i[4][8] = {};

    // QK mma warp atom: rows mrow..mrow+15, keys nkey..nkey+7
    const int mrow = (warp >> 2) * 16;
    const int nkey = (warp & 3) * 8;

    const float scale = 0.125f;  // 1/sqrt(64)

    for (int kt = 0; kt < LC_ / 32; kt++) {
        __syncthreads();   // prev PV done with sKr/sKi/sP; Q/stat init visible
        // ---- load K tile, convert to tf32 ----
        for (int i = tid; i < 32 * (HD_ / 4); i += 256) {
            int k = i >> 4;
            int d4 = (i & 15) * 4;
            size_t g = ((size_t)(b * LC_ + kt * 32 + k)) * F_ + h * HD_ + d4;
            float4 vr = *(const float4*)&g_Kr[g];
            float4 vi = *(const float4*)&g_Ki[g];
            vr.x = __uint_as_float(f2tf32(vr.x)); vr.y = __uint_as_float(f2tf32(vr.y));
            vr.z = __uint_as_float(f2tf32(vr.z)); vr.w = __uint_as_float(f2tf32(vr.w));
            vi.x = __uint_as_float(f2tf32(vi.x)); vi.y = __uint_as_float(f2tf32(vi.y));
            vi.z = __uint_as_float(f2tf32(vi.z)); vi.w = __uint_as_float(f2tf32(vi.w));
            *(float4*)&sKr[k * AST + d4] = vr;
            *(float4*)&sKi[k * AST + d4] = vi;
        }
        __syncthreads();

        // ---- QK via tf32 mma: S = Qr.Kr^T + Qi.Ki^T, Q exact via hi+lo ----
        {
            float c[4] = {0.f, 0.f, 0.f, 0.f};
#pragma unroll
            for (int d8 = 0; d8 < HD_; d8 += 8) {
                int ka = (nkey + qrow) * AST + d8 + qk;
                uint32_t br_[2], bi_[2];
                br_[0] = __float_as_uint(sKr[ka]);
                br_[1] = __float_as_uint(sKr[ka + 4]);
                bi_[0] = __float_as_uint(sKi[ka]);
                bi_[1] = __float_as_uint(sKi[ka + 4]);
                int a0 = (mrow + qrow) * AST + d8 + qk;
                int a1 = a0 + 8 * AST;
                uint32_t ahr[4] = { __float_as_uint(sQhr[a0]), __float_as_uint(sQhr[a1]),
                                    __float_as_uint(sQhr[a0 + 4]), __float_as_uint(sQhr[a1 + 4]) };
                uint32_t alr[4] = { __float_as_uint(sQlr[a0]), __float_as_uint(sQlr[a1]),
                                    __float_as_uint(sQlr[a0 + 4]), __float_as_uint(sQlr[a1 + 4]) };
                uint32_t ahi[4] = { __float_as_uint(sQhi_[a0]), __float_as_uint(sQhi_[a1]),
                                    __float_as_uint(sQhi_[a0 + 4]), __float_as_uint(sQhi_[a1 + 4]) };
                uint32_t ali[4] = { __float_as_uint(sQli[a0]), __float_as_uint(sQli[a1]),
                                    __float_as_uint(sQli[a0 + 4]), __float_as_uint(sQli[a1 + 4]) };
                mma_tf32(c, ahr, br_);
                mma_tf32(c, alr, br_);
                mma_tf32(c, ahi, bi_);
                mma_tf32(c, ali, bi_);
            }
            sP[(mrow + qrow)     * 33 + nkey + qk * 2]     = c[0];
            sP[(mrow + qrow)     * 33 + nkey + qk * 2 + 1] = c[1];
            sP[(mrow + qrow + 8) * 33 + nkey + qk * 2]     = c[2];
            sP[(mrow + qrow + 8) * 33 + nkey + qk * 2 + 1] = c[3];
        }
        __syncthreads();   // scores visible to softmax warps

        // ---- online softmax: warp -> 4 rows, lane -> key ----
        {
            const int r0 = warp * 4;
            float mv = mask ? ((1.0f - mask[b * LC_ + kt * 32 + lane]) * -1e9f) : 0.0f;
#pragma unroll
            for (int r = 0; r < 4; r++) {
                int q = r0 + r;
                float s = sP[q * 33 + lane] * scale + mv;
                float mx = s;
#pragma unroll
                for (int o = 16; o > 0; o >>= 1)
                    mx = fmaxf(mx, __shfl_xor_sync(0xffffffffu, mx, o));
                float m_old = sM[q];
                float m_new = fmaxf(m_old, mx);
                float p = __expf(s - m_new);
                float ps = p;
#pragma unroll
                for (int o = 16; o > 0; o >>= 1)
                    ps += __shfl_xor_sync(0xffffffffu, ps, o);
                sP[q * 33 + lane] = p;
                __syncwarp();
                if (lane == 0) {
                    float alpha = __expf(m_old - m_new);
                    sM[q] = m_new;
                    sL[q] = sL[q] * alpha + ps;
                    sAlpha[q] = alpha;
                }
                __syncwarp();
            }
        }
        __syncthreads();   // probs/alpha ready; mma reads of sK done

        // ---- load V tile (fp32) into K buffers ----
        for (int i = tid; i < 32 * (HD_ / 4); i += 256) {
            int k = i >> 4;
            int d4 = (i & 15) * 4;
            size_t g = ((size_t)(b * LC_ + kt * 32 + k)) * F_ + h * HD_ + d4;
            *(float4*)&sKr[k * AST + d4] = *(const float4*)&g_Vr[g];
            *(float4*)&sKi[k * AST + d4] = *(const float4*)&g_Vi[g];
        }
        __syncthreads();

        // ---- PV (fp32, broadcast-friendly) ----
        float al[4];
#pragma unroll
        for (int r = 0; r < 4; r++) al[r] = sAlpha[rg * 4 + r];
#pragma unroll
        for (int r = 0; r < 4; r++)
#pragma unroll
            for (int j = 0; j < 8; j++) { o_r[r][j] *= al[r]; o_i[r][j] *= al[r]; }

#pragma unroll
        for (int j = 0; j < 8; j++) {
            int k = ksub + 4 * j;
            float4 vr0 = *(const float4*)&sKr[k * AST + d0];
            float4 vr1 = *(const float4*)&sKr[k * AST + d0 + 4];
            float4 vi0 = *(const float4*)&sKi[k * AST + d0];
            float4 vi1 = *(const float4*)&sKi[k * AST + d0 + 4];
            float p[4];
#pragma unroll
            for (int r = 0; r < 4; r++) p[r] = sP[(rg * 4 + r) * 33 + k];
#pragma unroll
            for (int r = 0; r < 4; r++) {
                o_r[r][0] = fmaf(p[r], vr0.x, o_r[r][0]);
                o_r[r][1] = fmaf(p[r], vr0.y, o_r[r][1]);
                o_r[r][2] = fmaf(p[r], vr0.z, o_r[r][2]);
                o_r[r][3] = fmaf(p[r], vr0.w, o_r[r][3]);
                o_r[r][4] = fmaf(p[r], vr1.x, o_r[r][4]);
                o_r[r][5] = fmaf(p[r], vr1.y, o_r[r][5]);
                o_r[r][6] = fmaf(p[r], vr1.z, o_r[r][6]);
                o_r[r][7] = fmaf(p[r], vr1.w, o_r[r][7]);
                o_i[r][0] = fmaf(p[r], vi0.x, o_i[r][0]);
                o_i[r][1] = fmaf(p[r], vi0.y, o_i[r][1]);
                o_i[r][2] = fmaf(p[r], vi0.z, o_i[r][2]);
                o_i[r][3] = fmaf(p[r], vi0.w, o_i[r][3]);
                o_i[r][4] = fmaf(p[r], vi1.x, o_i[r][4]);
                o_i[r][5] = fmaf(p[r], vi1.y, o_i[r][5]);
                o_i[r][6] = fmaf(p[r], vi1.z, o_i[r][6]);
                o_i[r][7] = fmaf(p[r], vi1.w, o_i[r][7]);
            }
        }
    }
    __syncthreads();

    // k-split butterfly reduction across ksub
#pragma unroll
    for (int r = 0; r < 4; r++) {
#pragma unroll
        for (int j = 0; j < 8; j++) {
            float vr = o_r[r][j], vi = o_i[r][j];
            vr += __shfl_xor_sync(0xffffffffu, vr, 1);
            vi += __shfl_xor_sync(0xffffffffu, vi, 1);
            vr += __shfl_xor_sync(0xffffffffu, vr, 2);
            vi += __shfl_xor_sync(0xffffffffu, vi, 2);
            o_r[r][j] = vr; o_i[r][j] = vi;
        }
    }

#pragma unroll
    for (int r = 0; r < 4; r++) {
        int row = rg * 4 + r;
        float inv = 1.0f / sL[row];
        size_t g = ((size_t)(b * S_ + q0 + row)) * F_ + h * HD_ + d0;
#pragma unroll
        for (int t = 0; t < 2; t++) {
            int j = ksub * 2 + t;
            g_Or[g + j] = o_r[r][j] * inv;
            g_Oi[g + j] = o_i[r][j] * inv;
        }
    }
}

// Fallback: bounded zero-fill so graph capture always has nodes.
__global__ void fill_zero_kernel(float* p, long long n)
{
    long long i = (long long)blockIdx.x * blockDim.x + threadIdx.x;
    if (i < n) p[i] = 0.0f;
}

// ---------------- launch ----------------
extern "C" void kernel_launch(void* const* d_in, const int* in_sizes, int n_in,
                              void* d_out, int out_size)
{
    const long long MN = (long long)B_ * S_ * F_;

    const float* x4M[2]  = {0, 0}; int n4M = 0;
    const float* xctx[2] = {0, 0}; int nctx = 0;
    const float* pmask   = 0;
    const float* wF[4]   = {0, 0, 0, 0}; int nwF = 0;
    const float* wC[4]   = {0, 0, 0, 0}; int nwC = 0;
    const float* bias[8] = {0, 0, 0, 0, 0, 0, 0, 0}; int nb = 0;

    for (int i = 0; i < n_in; i++) {
        const float* p = (const float*)d_in[i];
        long long sz = in_sizes[i];
        if (sz == (long long)B_ * S_ * F_)        { if (n4M < 2) x4M[n4M++] = p; }
        else if (sz == (long long)B_ * LC_ * DC_) { if (nctx < 2) xctx[nctx++] = p; }
        else if (sz == (long long)B_ * LC_)       { pmask = p; }
        else if (sz == (long long)F_ * F_)        { if (nwF < 4) wF[nwF++] = p; }
        else if (sz == (long long)DC_ * F_)       { if (nwC < 4) wC[nwC++] = p; }
        else if (sz == (long long)F_)             { if (nb < 8) bias[nb++] = p; }
    }

    const float* x_r = x4M[0],  *x_i = x4M[1];
    const float* ctx_r = xctx[0], *ctx_i = xctx[1];
    const float* Wqr = wF[0], *Wqi = wF[1], *Wor = wF[2], *Woi = wF[3];
    const float* Wkr = wC[0], *Wki = wC[1], *Wvr = wC[2], *Wvi = wC[3];
    const float* bqr = bias[0], *bqi = bias[1];
    const float* bkr = bias[2], *bki = bias[3];
    const float* bvr = bias[4], *bvi = bias[5];
    const float* bor = bias[6], *boi = bias[7];

    int omode = ((long long)out_size >= 2 * MN) ? 2 : 1;

    if (!x_r || !x_i || !ctx_r || !ctx_i || !Wqr || !Wqi || !Wor || !Woi ||
        !Wkr || !Wki || !Wvr || !Wvi) {
        long long n = (omode == 2) ? 2 * MN : MN;
        fill_zero_kernel<<<(unsigned)((n + 255) / 256), 256>>>((float*)d_out, n);
        return;
    }

    cudaFuncSetAttribute(attn_kernel, cudaFuncAttributeMaxDynamicSharedMemorySize,
                         ATTN_SMEM_BYTES);

    dim3 blk(256);

    cgemm_kernel<0><<<dim3(F_ / 128, (B_ * S_) / 64), blk>>>(
        B_ * S_, F_, F_, x_r, x_i, Wqr, Wqi, bqr, bqi, nullptr, 0);
    cgemm_kernel<1><<<dim3(F_ / 128, (B_ * LC_) / 64), blk>>>(
        B_ * LC_, DC_, F_, ctx_r, ctx_i, Wkr, Wki, bkr, bki, nullptr, 0);
    cgemm_kernel<2><<<dim3(F_ / 128, (B_ * LC_) / 64), blk>>>(
        B_ * LC_, DC_, F_, ctx_r, ctx_i, Wvr, Wvi, bvr, bvi, nullptr, 0);

    attn_kernel<<<dim3(S_ / 32, B_ * H_), blk, ATTN_SMEM_BYTES>>>(pmask);

    cgemm_kernel<3><<<dim3(F_ / 128, (B_ * S_) / 64), blk>>>(
        B_ * S_, F_, F_, nullptr, nullptr, Wor, Woi, bor, boi, (float*)d_out, omode);
}

// round 12
// speedup vs baseline: 3.0538x; 1.4732x over previous
#include <cuda_runtime.h>
#include <math.h>
#include <stdint.h>

#define B_   2
#define S_   2048
#define LC_  1024
#define F_   1024
#define DC_  768
#define H_   16
#define HD_  64

// ---------------- scratch (no allocation allowed; zero-initialized) ----------------
__device__ __align__(16) float g_Qr[(size_t)B_ * S_ * F_];
__device__ __align__(16) float g_Qi[(size_t)B_ * S_ * F_];
__device__ __align__(16) float g_Kr[(size_t)B_ * LC_ * F_];
__device__ __align__(16) float g_Ki[(size_t)B_ * LC_ * F_];
__device__ __align__(16) float g_Vr[(size_t)B_ * LC_ * F_];
__device__ __align__(16) float g_Vi[(size_t)B_ * LC_ * F_];
__device__ __align__(16) float g_Or[(size_t)B_ * S_ * F_];
__device__ __align__(16) float g_Oi[(size_t)B_ * S_ * F_];
__device__ __align__(16) float g_S [(size_t)B_ * H_ * S_ * LC_];   // scores -> probs

// ---------------- tf32 mma helpers ----------------
__device__ __forceinline__ uint32_t f2tf32(float x) {
    uint32_t r;
    asm("cvt.rna.tf32.f32 %0, %1;" : "=r"(r) : "f"(x));
    return r;
}

__device__ __forceinline__ void mma_tf32(float c[4], const uint32_t a[4], const uint32_t b[2]) {
    asm volatile(
        "mma.sync.aligned.m16n8k8.row.col.f32.tf32.tf32.f32 "
        "{%0,%1,%2,%3}, {%4,%5,%6,%7}, {%8,%9}, {%0,%1,%2,%3};"
        : "+f"(c[0]), "+f"(c[1]), "+f"(c[2]), "+f"(c[3])
        : "r"(a[0]), "r"(a[1]), "r"(a[2]), "r"(a[3]), "r"(b[0]), "r"(b[1]));
}

// ---------------- complex GEMM via tf32 tensor cores (unchanged, proven) ----------------
#define SA_ST 20
#define SB_ST 136

template <int MODE>
__global__ void __launch_bounds__(256, 2) cgemm_kernel(
    int M, int K, int N,
    const float* __restrict__ Ap_r, const float* __restrict__ Ap_i,
    const float* __restrict__ Br, const float* __restrict__ Bi,
    const float* __restrict__ bbr, const float* __restrict__ bbi,
    float* __restrict__ outF, int omode)
{
    const float* __restrict__ Ar = (MODE == 3) ? g_Or : Ap_r;
    const float* __restrict__ Ai = (MODE == 3) ? g_Oi : Ap_i;

    __shared__ uint32_t sAr[64 * SA_ST];
    __shared__ uint32_t sAi[64 * SA_ST];
    __shared__ uint32_t sBr[16 * SB_ST];
    __shared__ uint32_t sBi[16 * SB_ST];
    __shared__ uint32_t sBni[16 * SB_ST];

    const int tid = threadIdx.x;
    const int warp = tid >> 5, lane = tid & 31;
    const int qrow = lane >> 2, qk = lane & 3;
    const int warpM = warp >> 2;
    const int warpN = warp & 3;
    const int m0 = blockIdx.y << 6;
    const int n0 = blockIdx.x << 7;

    float accr[2][4][4] = {};
    float acci[2][4][4] = {};

    const int lm = tid >> 4;
    const int lk = tid & 15;
    const int bn = tid & 127;
    const int bkb = tid >> 7;

    for (int k0 = 0; k0 < K; k0 += 16) {
#pragma unroll
        for (int j = 0; j < 4; j++) {
            int m = lm + j * 16;
            size_t g = (size_t)(m0 + m) * K + (k0 + lk);
            sAr[m * SA_ST + lk] = f2tf32(Ar[g]);
            sAi[m * SA_ST + lk] = f2tf32(Ai[g]);
        }
#pragma unroll
        for (int j = 0; j < 8; j++) {
            int kk = bkb + j * 2;
            size_t g = (size_t)(k0 + kk) * N + (n0 + bn);
            float vr = Br[g], vi = Bi[g];
            sBr[kk * SB_ST + bn]  = f2tf32(vr);
            sBi[kk * SB_ST + bn]  = f2tf32(vi);
            sBni[kk * SB_ST + bn] = f2tf32(-vi);
        }
        __syncthreads();

#pragma unroll
        for (int kc = 0; kc < 16; kc += 8) {
            uint32_t ar[2][4], ai[2][4];
#pragma unroll
            for (int ma = 0; ma < 2; ma++) {
                int mb = warpM * 32 + ma * 16 + qrow;
                ar[ma][0] = sAr[(mb)     * SA_ST + kc + qk];
                ar[ma][1] = sAr[(mb + 8) * SA_ST + kc + qk];
                ar[ma][2] = sAr[(mb)     * SA_ST + kc + qk + 4];
                ar[ma][3] = sAr[(mb + 8) * SA_ST + kc + qk + 4];
                ai[ma][0] = sAi[(mb)     * SA_ST + kc + qk];
                ai[ma][1] = sAi[(mb + 8) * SA_ST + kc + qk];
                ai[ma][2] = sAi[(mb)     * SA_ST + kc + qk + 4];
                ai[ma][3] = sAi[(mb + 8) * SA_ST + kc + qk + 4];
            }
#pragma unroll
            for (int na = 0; na < 4; na++) {
                int nb = warpN * 32 + na * 8 + qrow;
                uint32_t br_[2], bi_[2], bni_[2];
                br_[0]  = sBr[(kc + qk)     * SB_ST + nb];
                br_[1]  = sBr[(kc + qk + 4) * SB_ST + nb];
                bi_[0]  = sBi[(kc + qk)     * SB_ST + nb];
                bi_[1]  = sBi[(kc + qk + 4) * SB_ST + nb];
                bni_[0] = sBni[(kc + qk)     * SB_ST + nb];
                bni_[1] = sBni[(kc + qk + 4) * SB_ST + nb];
#pragma unroll
                for (int ma = 0; ma < 2; ma++) {
                    mma_tf32(accr[ma][na], ar[ma], br_);
                    mma_tf32(accr[ma][na], ai[ma], bni_);
                    mma_tf32(acci[ma][na], ar[ma], bi_);
                    mma_tf32(acci[ma][na], ai[ma], br_);
                }
            }
        }
        __syncthreads();
    }

#pragma unroll
    for (int ma = 0; ma < 2; ma++) {
#pragma unroll
        for (int na = 0; na < 4; na++) {
#pragma unroll
            for (int c = 0; c < 4; c++) {
                int row = m0 + warpM * 32 + ma * 16 + qrow + ((c >= 2) ? 8 : 0);
                int col = n0 + warpN * 32 + na * 8 + qk * 2 + (c & 1);
                float vr = accr[ma][na][c] + (bbr ? bbr[col] : 0.0f);
                float vi = acci[ma][na][c] + (bbi ? bbi[col] : 0.0f);
                size_t idx = (size_t)row * N + col;
                if (MODE == 0)      { g_Qr[idx] = vr; g_Qi[idx] = vi; }
                else if (MODE == 1) { g_Kr[idx] = vr; g_Ki[idx] = vi; }
                else if (MODE == 2) { g_Vr[idx] = vr; g_Vi[idx] = vi; }
                else {
                    if (omode == 2) { outF[2 * idx] = vr; outF[2 * idx + 1] = vi; }
                    else            { outF[idx] = vr; }
                }
            }
        }
    }
}

// ---------------- QK batched GEMM: S = (Qr.Kr^T + Qi.Ki^T) * scale ----------------
// Per batch (b,h): M=S_, N=LC_, Kdim=128 ([Qr|Qi] x [Kr|Ki] concat along K).
// Tile 64m x 128n, K-step 16, 256 threads, Q split hi/lo tf32 (2 chains).
__global__ void __launch_bounds__(256, 2) qk_kernel()
{
    __shared__ uint32_t sAh[64 * SA_ST];
    __shared__ uint32_t sAl[64 * SA_ST];
    __shared__ uint32_t sB [16 * SB_ST];

    const int tid = threadIdx.x;
    const int warp = tid >> 5, lane = tid & 31;
    const int qrow = lane >> 2, qk = lane & 3;
    const int warpM = warp >> 2;
    const int warpN = warp & 3;
    const int m0 = blockIdx.y << 6;       // s tile
    const int n0 = blockIdx.x << 7;       // lc tile
    const int b  = blockIdx.z >> 4;
    const int h  = blockIdx.z & 15;

    float acc[2][4][4] = {};

    const int dd = tid & 15;              // k within step
    const int t16 = tid >> 4;             // 0..15

    for (int k0 = 0; k0 < 128; k0 += 16) {
        const float* __restrict__ Qsrc = (k0 < 64) ? g_Qr : g_Qi;
        const float* __restrict__ Ksrc = (k0 < 64) ? g_Kr : g_Ki;
        const int dbase = (k0 & 63);
        // A tile: 64 s-rows x 16 k (d contiguous in global)
#pragma unroll
        for (int j = 0; j < 4; j++) {
            int m = t16 + j * 16;
            float v = Qsrc[((size_t)(b * S_ + m0 + m)) * F_ + h * HD_ + dbase + dd];
            uint32_t hb = f2tf32(v);
            sAh[m * SA_ST + dd] = hb;
            sAl[m * SA_ST + dd] = f2tf32(v - __uint_as_float(hb));
        }
        // B tile: 16 k x 128 n (lc rows, d contiguous in global -> transpose)
#pragma unroll
        for (int j = 0; j < 8; j++) {
            int n = t16 + j * 16;
            float v = Ksrc[((size_t)(b * LC_ + n0 + n)) * F_ + h * HD_ + dbase + dd];
            sB[dd * SB_ST + n] = f2tf32(v);
        }
        __syncthreads();

#pragma unroll
        for (int kc = 0; kc < 16; kc += 8) {
            uint32_t ah[2][4], al[2][4];
#pragma unroll
            for (int ma = 0; ma < 2; ma++) {
                int mb = warpM * 32 + ma * 16 + qrow;
                ah[ma][0] = sAh[(mb)     * SA_ST + kc + qk];
                ah[ma][1] = sAh[(mb + 8) * SA_ST + kc + qk];
                ah[ma][2] = sAh[(mb)     * SA_ST + kc + qk + 4];
                ah[ma][3] = sAh[(mb + 8) * SA_ST + kc + qk + 4];
                al[ma][0] = sAl[(mb)     * SA_ST + kc + qk];
                al[ma][1] = sAl[(mb + 8) * SA_ST + kc + qk];
                al[ma][2] = sAl[(mb)     * SA_ST + kc + qk + 4];
                al[ma][3] = sAl[(mb + 8) * SA_ST + kc + qk + 4];
            }
#pragma unroll
            for (int na = 0; na < 4; na++) {
                int nb = warpN * 32 + na * 8 + qrow;
                uint32_t bb[2];
                bb[0] = sB[(kc + qk)     * SB_ST + nb];
                bb[1] = sB[(kc + qk + 4) * SB_ST + nb];
#pragma unroll
                for (int ma = 0; ma < 2; ma++) {
                    mma_tf32(acc[ma][na], ah[ma], bb);
                    mma_tf32(acc[ma][na], al[ma], bb);
                }
            }
        }
        __syncthreads();
    }

    float* Sdst = g_S + (size_t)(b * H_ + h) * S_ * LC_;
#pragma unroll
    for (int ma = 0; ma < 2; ma++) {
#pragma unroll
        for (int na = 0; na < 4; na++) {
#pragma unroll
            for (int c = 0; c < 4; c++) {
                int row = m0 + warpM * 32 + ma * 16 + qrow + ((c >= 2) ? 8 : 0);
                int col = n0 + warpN * 32 + na * 8 + qk * 2 + (c & 1);
                Sdst[(size_t)row * LC_ + col] = acc[ma][na][c] * 0.125f;
            }
        }
    }
}

// ---------------- softmax: one warp per row, row in registers ----------------
__global__ void __launch_bounds__(256) softmax_kernel(const float* __restrict__ mask)
{
    const int warp = threadIdx.x >> 5, lane = threadIdx.x & 31;
    const long long row = (long long)blockIdx.x * 8 + warp;   // < B*H*S
    const int b = (int)(row >> 15);                           // H*S = 32768 rows per batch
    float* Srow = g_S + row * LC_;

    float4 v[8];
    float mx = -1e30f;
#pragma unroll
    for (int j = 0; j < 8; j++) {
        int idx = lane * 4 + j * 128;
        v[j] = *(const float4*)&Srow[idx];
        if (mask) {
            float4 mk = *(const float4*)&mask[b * LC_ + idx];
            v[j].x += (1.0f - mk.x) * -1e9f;
            v[j].y += (1.0f - mk.y) * -1e9f;
            v[j].z += (1.0f - mk.z) * -1e9f;
            v[j].w += (1.0f - mk.w) * -1e9f;
        }
        mx = fmaxf(mx, fmaxf(fmaxf(v[j].x, v[j].y), fmaxf(v[j].z, v[j].w)));
    }
#pragma unroll
    for (int o = 16; o > 0; o >>= 1)
        mx = fmaxf(mx, __shfl_xor_sync(0xffffffffu, mx, o));

    float l = 0.0f;
#pragma unroll
    for (int j = 0; j < 8; j++) {
        v[j].x = __expf(v[j].x - mx);
        v[j].y = __expf(v[j].y - mx);
        v[j].z = __expf(v[j].z - mx);
        v[j].w = __expf(v[j].w - mx);
        l += v[j].x + v[j].y + v[j].z + v[j].w;
    }
#pragma unroll
    for (int o = 16; o > 0; o >>= 1)
        l += __shfl_xor_sync(0xffffffffu, l, o);
    float inv = 1.0f / l;

#pragma unroll
    for (int j = 0; j < 8; j++) {
        int idx = lane * 4 + j * 128;
        float4 p = v[j];
        p.x *= inv; p.y *= inv; p.z *= inv; p.w *= inv;
        *(float4*)&Srow[idx] = p;
    }
}

// ---------------- PV batched GEMM: O = P @ [Vr|Vi], P & V hi/lo (3 chains) ----------------
// Per batch (b,h): M=S_, N=128 ([Vr|Vi]), Kdim=LC_. Tile 64m x 128n, K-step 16.
__global__ void __launch_bounds__(256, 2) pv_kernel()
{
    __shared__ uint32_t sPh[64 * SA_ST];
    __shared__ uint32_t sPl[64 * SA_ST];
    __shared__ uint32_t sBh[16 * SB_ST];
    __shared__ uint32_t sBl[16 * SB_ST];

    const int tid = threadIdx.x;
    const int warp = tid >> 5, lane = tid & 31;
    const int qrow = lane >> 2, qk = lane & 3;
    const int warpM = warp >> 2;
    const int warpN = warp & 3;
    const int m0 = blockIdx.y << 6;       // s tile
    const int b  = blockIdx.z >> 4;
    const int h  = blockIdx.z & 15;

    const float* __restrict__ Psrc = g_S + (size_t)(b * H_ + h) * S_ * LC_;

    float acc[2][4][4] = {};

    const int lm = tid >> 4;
    const int lk = tid & 15;
    const int bn = tid & 127;
    const int bkb = tid >> 7;

    for (int k0 = 0; k0 < LC_; k0 += 16) {
        // A tile: P 64 x 16 (lc contiguous), hi/lo split
#pragma unroll
        for (int j = 0; j < 4; j++) {
            int m = lm + j * 16;
            float v = Psrc[(size_t)(m0 + m) * LC_ + k0 + lk];
            uint32_t hb = f2tf32(v);
            sPh[m * SA_ST + lk] = hb;
            sPl[m * SA_ST + lk] = f2tf32(v - __uint_as_float(hb));
        }
        // B tile: [Vr|Vi] 16 x 128 (d contiguous within halves), hi/lo split
#pragma unroll
        for (int j = 0; j < 8; j++) {
            int kk = bkb + j * 2;
            const float* __restrict__ Vsrc = (bn < 64) ? g_Vr : g_Vi;
            float v = Vsrc[((size_t)(b * LC_ + k0 + kk)) * F_ + h * HD_ + (bn & 63)];
            uint32_t hb = f2tf32(v);
            sBh[kk * SB_ST + bn] = hb;
            sBl[kk * SB_ST + bn] = f2tf32(v - __uint_as_float(hb));
        }
        __syncthreads();

#pragma unroll
        for (int kc = 0; kc < 16; kc += 8) {
            uint32_t ph[2][4], pl[2][4];
#pragma unroll
            for (int ma = 0; ma < 2; ma++) {
                int mb = warpM * 32 + ma * 16 + qrow;
                ph[ma][0] = sPh[(mb)     * SA_ST + kc + qk];
                ph[ma][1] = sPh[(mb + 8) * SA_ST + kc + qk];
                ph[ma][2] = sPh[(mb)     * SA_ST + kc + qk + 4];
                ph[ma][3] = sPh[(mb + 8) * SA_ST + kc + qk + 4];
                pl[ma][0] = sPl[(mb)     * SA_ST + kc + qk];
                pl[ma][1] = sPl[(mb + 8) * SA_ST + kc + qk];
                pl[ma][2] = sPl[(mb)     * SA_ST + kc + qk + 4];
                pl[ma][3] = sPl[(mb + 8) * SA_ST + kc + qk + 4];
            }
#pragma unroll
            for (int na = 0; na < 4; na++) {
                int nb = warpN * 32 + na * 8 + qrow;
                uint32_t bh[2], bl[2];
                bh[0] = sBh[(kc + qk)     * SB_ST + nb];
                bh[1] = sBh[(kc + qk + 4) * SB_ST + nb];
                bl[0] = sBl[(kc + qk)     * SB_ST + nb];
                bl[1] = sBl[(kc + qk + 4) * SB_ST + nb];
#pragma unroll
                for (int ma = 0; ma < 2; ma++) {
                    mma_tf32(acc[ma][na], ph[ma], bh);
                    mma_tf32(acc[ma][na], ph[ma], bl);
                    mma_tf32(acc[ma][na], pl[ma], bh);
                }
            }
        }
        __syncthreads();
    }

#pragma unroll
    for (int ma = 0; ma < 2; ma++) {
#pragma unroll
        for (int na = 0; na < 4; na++) {
#pragma unroll
            for (int c = 0; c < 4; c++) {
                int row = m0 + warpM * 32 + ma * 16 + qrow + ((c >= 2) ? 8 : 0);
                int col = warpN * 32 + na * 8 + qk * 2 + (c & 1);
                size_t g = ((size_t)(b * S_ + row)) * F_ + h * HD_ + (col & 63);
                if (col < 64) g_Or[g] = acc[ma][na][c];
                else          g_Oi[g] = acc[ma][na][c];
            }
        }
    }
}

// Fallback: bounded zero-fill so graph capture always has nodes.
__global__ void fill_zero_kernel(float* p, long long n)
{
    long long i = (long long)blockIdx.x * blockDim.x + threadIdx.x;
    if (i < n) p[i] = 0.0f;
}

// ---------------- launch ----------------
extern "C" void kernel_launch(void* const* d_in, const int* in_sizes, int n_in,
                              void* d_out, int out_size)
{
    const long long MN = (long long)B_ * S_ * F_;

    const float* x4M[2]  = {0, 0}; int n4M = 0;
    const float* xctx[2] = {0, 0}; int nctx = 0;
    const float* pmask   = 0;
    const float* wF[4]   = {0, 0, 0, 0}; int nwF = 0;
    const float* wC[4]   = {0, 0, 0, 0}; int nwC = 0;
    const float* bias[8] = {0, 0, 0, 0, 0, 0, 0, 0}; int nb = 0;

    for (int i = 0; i < n_in; i++) {
        const float* p = (const float*)d_in[i];
        long long sz = in_sizes[i];
        if (sz == (long long)B_ * S_ * F_)        { if (n4M < 2) x4M[n4M++] = p; }
        else if (sz == (long long)B_ * LC_ * DC_) { if (nctx < 2) xctx[nctx++] = p; }
        else if (sz == (long long)B_ * LC_)       { pmask = p; }
        else if (sz == (long long)F_ * F_)        { if (nwF < 4) wF[nwF++] = p; }
        else if (sz == (long long)DC_ * F_)       { if (nwC < 4) wC[nwC++] = p; }
        else if (sz == (long long)F_)             { if (nb < 8) bias[nb++] = p; }
    }

    const float* x_r = x4M[0],  *x_i = x4M[1];
    const float* ctx_r = xctx[0], *ctx_i = xctx[1];
    const float* Wqr = wF[0], *Wqi = wF[1], *Wor = wF[2], *Woi = wF[3];
    const float* Wkr = wC[0], *Wki = wC[1], *Wvr = wC[2], *Wvi = wC[3];
    const float* bqr = bias[0], *bqi = bias[1];
    const float* bkr = bias[2], *bki = bias[3];
    const float* bvr = bias[4], *bvi = bias[5];
    const float* bor = bias[6], *boi = bias[7];

    int omode = ((long long)out_size >= 2 * MN) ? 2 : 1;

    if (!x_r || !x_i || !ctx_r || !ctx_i || !Wqr || !Wqi || !Wor || !Woi ||
        !Wkr || !Wki || !Wvr || !Wvi) {
        long long n = (omode == 2) ? 2 * MN : MN;
        fill_zero_kernel<<<(unsigned)((n + 255) / 256), 256>>>((float*)d_out, n);
        return;
    }

    dim3 blk(256);

    // projections
    cgemm_kernel<0><<<dim3(F_ / 128, (B_ * S_) / 64), blk>>>(
        B_ * S_, F_, F_, x_r, x_i, Wqr, Wqi, bqr, bqi, nullptr, 0);
    cgemm_kernel<1><<<dim3(F_ / 128, (B_ * LC_) / 64), blk>>>(
        B_ * LC_, DC_, F_, ctx_r, ctx_i, Wkr, Wki, bkr, bki, nullptr, 0);
    cgemm_kernel<2><<<dim3(F_ / 128, (B_ * LC_) / 64), blk>>>(
        B_ * LC_, DC_, F_, ctx_r, ctx_i, Wvr, Wvi, bvr, bvi, nullptr, 0);

    // attention as 3 specialized kernels
    qk_kernel<<<dim3(LC_ / 128, S_ / 64, B_ * H_), blk>>>();
    softmax_kernel<<<(B_ * H_ * S_) / 8, blk>>>(pmask);
    pv_kernel<<<dim3(1, S_ / 64, B_ * H_), blk>>>();

    // output projection
    cgemm_kernel<3><<<dim3(F_ / 128, (B_ * S_) / 64), blk>>>(
        B_ * S_, F_, F_, nullptr, nullptr, Wor, Woi, bor, boi, (float*)d_out, omode);
}

// round 13
// speedup vs baseline: 3.1943x; 1.0460x over previous
#include <cuda_runtime.h>
#include <math.h>
#include <stdint.h>

#define B_   2
#define S_   2048
#define LC_  1024
#define F_   1024
#define DC_  768
#define H_   16
#define HD_  64

// ---------------- scratch (no allocation allowed; zero-initialized) ----------------
__device__ __align__(16) float g_Qr[(size_t)B_ * S_ * F_];
__device__ __align__(16) float g_Qi[(size_t)B_ * S_ * F_];
__device__ __align__(16) float g_Kr[(size_t)B_ * LC_ * F_];
__device__ __align__(16) float g_Ki[(size_t)B_ * LC_ * F_];
__device__ __align__(16) float g_Vr[(size_t)B_ * LC_ * F_];
__device__ __align__(16) float g_Vi[(size_t)B_ * LC_ * F_];
__device__ __align__(16) float g_Or[(size_t)B_ * S_ * F_];
__device__ __align__(16) float g_Oi[(size_t)B_ * S_ * F_];
__device__ __align__(16) float g_S [(size_t)B_ * H_ * S_ * LC_];   // scores -> probs

// ---------------- tf32 mma helpers ----------------
__device__ __forceinline__ uint32_t f2tf32(float x) {
    uint32_t r;
    asm("cvt.rna.tf32.f32 %0, %1;" : "=r"(r) : "f"(x));
    return r;
}

__device__ __forceinline__ void mma_tf32(float c[4], const uint32_t a[4], const uint32_t b[2]) {
    asm volatile(
        "mma.sync.aligned.m16n8k8.row.col.f32.tf32.tf32.f32 "
        "{%0,%1,%2,%3}, {%4,%5,%6,%7}, {%8,%9}, {%0,%1,%2,%3};"
        : "+f"(c[0]), "+f"(c[1]), "+f"(c[2]), "+f"(c[3])
        : "r"(a[0]), "r"(a[1]), "r"(a[2]), "r"(a[3]), "r"(b[0]), "r"(b[1]));
}

// ---------------- complex GEMM via tf32 tensor cores (software-pipelined) ----------------
#define SA_ST 20
#define SB_ST 136

template <int MODE>
__global__ void __launch_bounds__(256, 2) cgemm_kernel(
    int M, int K, int N,
    const float* __restrict__ Ap_r, const float* __restrict__ Ap_i,
    const float* __restrict__ Br, const float* __restrict__ Bi,
    const float* __restrict__ bbr, const float* __restrict__ bbi,
    float* __restrict__ outF, int omode)
{
    const float* __restrict__ Ar = (MODE == 3) ? g_Or : Ap_r;
    const float* __restrict__ Ai = (MODE == 3) ? g_Oi : Ap_i;

    __shared__ uint32_t sAr[64 * SA_ST];
    __shared__ uint32_t sAi[64 * SA_ST];
    __shared__ uint32_t sBr[16 * SB_ST];
    __shared__ uint32_t sBi[16 * SB_ST];
    __shared__ uint32_t sBni[16 * SB_ST];

    const int tid = threadIdx.x;
    const int warp = tid >> 5, lane = tid & 31;
    const int qrow = lane >> 2, qk = lane & 3;
    const int warpM = warp >> 2;
    const int warpN = warp & 3;
    const int m0 = blockIdx.y << 6;
    const int n0 = blockIdx.x << 7;

    float accr[2][4][4] = {};
    float acci[2][4][4] = {};

    const int lm = tid >> 4;
    const int lk = tid & 15;
    const int bn = tid & 127;
    const int bkb = tid >> 7;

    // prefetch registers
    float pa_r[4], pa_i[4], pb_r[8], pb_i[8];

    auto load_g = [&](int k0) {
#pragma unroll
        for (int j = 0; j < 4; j++) {
            int m = lm + j * 16;
            size_t g = (size_t)(m0 + m) * K + (k0 + lk);
            pa_r[j] = Ar[g];
            pa_i[j] = Ai[g];
        }
#pragma unroll
        for (int j = 0; j < 8; j++) {
            int kk = bkb + j * 2;
            size_t g = (size_t)(k0 + kk) * N + (n0 + bn);
            pb_r[j] = Br[g];
            pb_i[j] = Bi[g];
        }
    };
    auto store_s = [&]() {
#pragma unroll
        for (int j = 0; j < 4; j++) {
            int m = lm + j * 16;
            sAr[m * SA_ST + lk] = f2tf32(pa_r[j]);
            sAi[m * SA_ST + lk] = f2tf32(pa_i[j]);
        }
#pragma unroll
        for (int j = 0; j < 8; j++) {
            int kk = bkb + j * 2;
            sBr[kk * SB_ST + bn]  = f2tf32(pb_r[j]);
            sBi[kk * SB_ST + bn]  = f2tf32(pb_i[j]);
            sBni[kk * SB_ST + bn] = f2tf32(-pb_i[j]);
        }
    };

    load_g(0);
    store_s();
    __syncthreads();

    for (int k0 = 0; k0 < K; k0 += 16) {
        const bool more = (k0 + 16 < K);
        if (more) load_g(k0 + 16);    // gmem latency overlaps mma phase

#pragma unroll
        for (int kc = 0; kc < 16; kc += 8) {
            uint32_t ar[2][4], ai[2][4];
#pragma unroll
            for (int ma = 0; ma < 2; ma++) {
                int mb = warpM * 32 + ma * 16 + qrow;
                ar[ma][0] = sAr[(mb)     * SA_ST + kc + qk];
                ar[ma][1] = sAr[(mb + 8) * SA_ST + kc + qk];
                ar[ma][2] = sAr[(mb)     * SA_ST + kc + qk + 4];
                ar[ma][3] = sAr[(mb + 8) * SA_ST + kc + qk + 4];
                ai[ma][0] = sAi[(mb)     * SA_ST + kc + qk];
                ai[ma][1] = sAi[(mb + 8) * SA_ST + kc + qk];
                ai[ma][2] = sAi[(mb)     * SA_ST + kc + qk + 4];
                ai[ma][3] = sAi[(mb + 8) * SA_ST + kc + qk + 4];
            }
#pragma unroll
            for (int na = 0; na < 4; na++) {
                int nb = warpN * 32 + na * 8 + qrow;
                uint32_t br_[2], bi_[2], bni_[2];
                br_[0]  = sBr[(kc + qk)     * SB_ST + nb];
                br_[1]  = sBr[(kc + qk + 4) * SB_ST + nb];
                bi_[0]  = sBi[(kc + qk)     * SB_ST + nb];
                bi_[1]  = sBi[(kc + qk + 4) * SB_ST + nb];
                bni_[0] = sBni[(kc + qk)     * SB_ST + nb];
                bni_[1] = sBni[(kc + qk + 4) * SB_ST + nb];
#pragma unroll
                for (int ma = 0; ma < 2; ma++) {
                    mma_tf32(accr[ma][na], ar[ma], br_);
                    mma_tf32(accr[ma][na], ai[ma], bni_);
                    mma_tf32(acci[ma][na], ar[ma], bi_);
                    mma_tf32(acci[ma][na], ai[ma], br_);
                }
            }
        }

        if (more) {
            __syncthreads();   // all warps done reading current tile
            store_s();
            __syncthreads();   // new tile visible
        }
    }

#pragma unroll
    for (int ma = 0; ma < 2; ma++) {
#pragma unroll
        for (int na = 0; na < 4; na++) {
#pragma unroll
            for (int c = 0; c < 4; c++) {
                int row = m0 + warpM * 32 + ma * 16 + qrow + ((c >= 2) ? 8 : 0);
                int col = n0 + warpN * 32 + na * 8 + qk * 2 + (c & 1);
                float vr = accr[ma][na][c] + (bbr ? bbr[col] : 0.0f);
                float vi = acci[ma][na][c] + (bbi ? bbi[col] : 0.0f);
                size_t idx = (size_t)row * N + col;
                if (MODE == 0)      { g_Qr[idx] = vr; g_Qi[idx] = vi; }
                else if (MODE == 1) { g_Kr[idx] = vr; g_Ki[idx] = vi; }
                else if (MODE == 2) { g_Vr[idx] = vr; g_Vi[idx] = vi; }
                else {
                    if (omode == 2) { outF[2 * idx] = vr; outF[2 * idx + 1] = vi; }
                    else            { outF[idx] = vr; }
                }
            }
        }
    }
}

// ---------------- QK batched GEMM (pipelined): S = (Qr.Kr^T + Qi.Ki^T) * scale ----------------
__global__ void __launch_bounds__(256, 2) qk_kernel()
{
    __shared__ uint32_t sAh[64 * SA_ST];
    __shared__ uint32_t sAl[64 * SA_ST];
    __shared__ uint32_t sB [16 * SB_ST];

    const int tid = threadIdx.x;
    const int warp = tid >> 5, lane = tid & 31;
    const int qrow = lane >> 2, qk = lane & 3;
    const int warpM = warp >> 2;
    const int warpN = warp & 3;
    const int m0 = blockIdx.y << 6;       // s tile
    const int n0 = blockIdx.x << 7;       // lc tile
    const int b  = blockIdx.z >> 4;
    const int h  = blockIdx.z & 15;

    float acc[2][4][4] = {};

    const int dd = tid & 15;
    const int t16 = tid >> 4;

    float pa[4], pb[8];

    auto load_g = [&](int k0) {
        const float* __restrict__ Qsrc = (k0 < 64) ? g_Qr : g_Qi;
        const float* __restrict__ Ksrc = (k0 < 64) ? g_Kr : g_Ki;
        const int dbase = (k0 & 63);
#pragma unroll
        for (int j = 0; j < 4; j++) {
            int m = t16 + j * 16;
            pa[j] = Qsrc[((size_t)(b * S_ + m0 + m)) * F_ + h * HD_ + dbase + dd];
        }
#pragma unroll
        for (int j = 0; j < 8; j++) {
            int n = t16 + j * 16;
            pb[j] = Ksrc[((size_t)(b * LC_ + n0 + n)) * F_ + h * HD_ + dbase + dd];
        }
    };
    auto store_s = [&]() {
#pragma unroll
        for (int j = 0; j < 4; j++) {
            int m = t16 + j * 16;
            uint32_t hb = f2tf32(pa[j]);
            sAh[m * SA_ST + dd] = hb;
            sAl[m * SA_ST + dd] = f2tf32(pa[j] - __uint_as_float(hb));
        }
#pragma unroll
        for (int j = 0; j < 8; j++) {
            int n = t16 + j * 16;
            sB[dd * SB_ST + n] = f2tf32(pb[j]);
        }
    };

    load_g(0);
    store_s();
    __syncthreads();

    for (int k0 = 0; k0 < 128; k0 += 16) {
        const bool more = (k0 + 16 < 128);
        if (more) load_g(k0 + 16);

#pragma unroll
        for (int kc = 0; kc < 16; kc += 8) {
            uint32_t ah[2][4], al[2][4];
#pragma unroll
            for (int ma = 0; ma < 2; ma++) {
                int mb = warpM * 32 + ma * 16 + qrow;
                ah[ma][0] = sAh[(mb)     * SA_ST + kc + qk];
                ah[ma][1] = sAh[(mb + 8) * SA_ST + kc + qk];
                ah[ma][2] = sAh[(mb)     * SA_ST + kc + qk + 4];
                ah[ma][3] = sAh[(mb + 8) * SA_ST + kc + qk + 4];
                al[ma][0] = sAl[(mb)     * SA_ST + kc + qk];
                al[ma][1] = sAl[(mb + 8) * SA_ST + kc + qk];
                al[ma][2] = sAl[(mb)     * SA_ST + kc + qk + 4];
                al[ma][3] = sAl[(mb + 8) * SA_ST + kc + qk + 4];
            }
#pragma unroll
            for (int na = 0; na < 4; na++) {
                int nb = warpN * 32 + na * 8 + qrow;
                uint32_t bb[2];
                bb[0] = sB[(kc + qk)     * SB_ST + nb];
                bb[1] = sB[(kc + qk + 4) * SB_ST + nb];
#pragma unroll
                for (int ma = 0; ma < 2; ma++) {
                    mma_tf32(acc[ma][na], ah[ma], bb);
                    mma_tf32(acc[ma][na], al[ma], bb);
                }
            }
        }

        if (more) {
            __syncthreads();
            store_s();
            __syncthreads();
        }
    }

    float* Sdst = g_S + (size_t)(b * H_ + h) * S_ * LC_;
#pragma unroll
    for (int ma = 0; ma < 2; ma++) {
#pragma unroll
        for (int na = 0; na < 4; na++) {
#pragma unroll
            for (int c = 0; c < 4; c++) {
                int row = m0 + warpM * 32 + ma * 16 + qrow + ((c >= 2) ? 8 : 0);
                int col = n0 + warpN * 32 + na * 8 + qk * 2 + (c & 1);
                Sdst[(size_t)row * LC_ + col] = acc[ma][na][c] * 0.125f;
            }
        }
    }
}

// ---------------- softmax: one warp per row, row in registers ----------------
__global__ void __launch_bounds__(256) softmax_kernel(const float* __restrict__ mask)
{
    const int warp = threadIdx.x >> 5, lane = threadIdx.x & 31;
    const long long row = (long long)blockIdx.x * 8 + warp;   // < B*H*S
    const int b = (int)(row >> 15);                           // H*S = 32768 rows per batch
    float* Srow = g_S + row * LC_;

    float4 v[8];
    float mx = -1e30f;
#pragma unroll
    for (int j = 0; j < 8; j++) {
        int idx = lane * 4 + j * 128;
        v[j] = *(const float4*)&Srow[idx];
        if (mask) {
            float4 mk = *(const float4*)&mask[b * LC_ + idx];
            v[j].x += (1.0f - mk.x) * -1e9f;
            v[j].y += (1.0f - mk.y) * -1e9f;
            v[j].z += (1.0f - mk.z) * -1e9f;
            v[j].w += (1.0f - mk.w) * -1e9f;
        }
        mx = fmaxf(mx, fmaxf(fmaxf(v[j].x, v[j].y), fmaxf(v[j].z, v[j].w)));
    }
#pragma unroll
    for (int o = 16; o > 0; o >>= 1)
        mx = fmaxf(mx, __shfl_xor_sync(0xffffffffu, mx, o));

    float l = 0.0f;
#pragma unroll
    for (int j = 0; j < 8; j++) {
        v[j].x = __expf(v[j].x - mx);
        v[j].y = __expf(v[j].y - mx);
        v[j].z = __expf(v[j].z - mx);
        v[j].w = __expf(v[j].w - mx);
        l += v[j].x + v[j].y + v[j].z + v[j].w;
    }
#pragma unroll
    for (int o = 16; o > 0; o >>= 1)
        l += __shfl_xor_sync(0xffffffffu, l, o);
    float inv = 1.0f / l;

#pragma unroll
    for (int j = 0; j < 8; j++) {
        int idx = lane * 4 + j * 128;
        float4 p = v[j];
        p.x *= inv; p.y *= inv; p.z *= inv; p.w *= inv;
        *(float4*)&Srow[idx] = p;
    }
}

// ---------------- PV batched GEMM (pipelined): O = P @ [Vr|Vi], 3 chains ----------------
__global__ void __launch_bounds__(256, 2) pv_kernel()
{
    __shared__ uint32_t sPh[64 * SA_ST];
    __shared__ uint32_t sPl[64 * SA_ST];
    __shared__ uint32_t sBh[16 * SB_ST];
    __shared__ uint32_t sBl[16 * SB_ST];

    const int tid = threadIdx.x;
    const int warp = tid >> 5, lane = tid & 31;
    const int qrow = lane >> 2, qk = lane & 3;
    const int warpM = warp >> 2;
    const int warpN = warp & 3;
    const int m0 = blockIdx.y << 6;       // s tile
    const int b  = blockIdx.z >> 4;
    const int h  = blockIdx.z & 15;

    const float* __restrict__ Psrc = g_S + (size_t)(b * H_ + h) * S_ * LC_;

    float acc[2][4][4] = {};

    const int lm = tid >> 4;
    const int lk = tid & 15;
    const int bn = tid & 127;
    const int bkb = tid >> 7;

    float pa[4], pb[8];

    auto load_g = [&](int k0) {
#pragma unroll
        for (int j = 0; j < 4; j++) {
            int m = lm + j * 16;
            pa[j] = Psrc[(size_t)(m0 + m) * LC_ + k0 + lk];
        }
        const float* __restrict__ Vsrc = (bn < 64) ? g_Vr : g_Vi;
#pragma unroll
        for (int j = 0; j < 8; j++) {
            int kk = bkb + j * 2;
            pb[j] = Vsrc[((size_t)(b * LC_ + k0 + kk)) * F_ + h * HD_ + (bn & 63)];
        }
    };
    auto store_s = [&]() {
#pragma unroll
        for (int j = 0; j < 4; j++) {
            int m = lm + j * 16;
            uint32_t hb = f2tf32(pa[j]);
            sPh[m * SA_ST + lk] = hb;
            sPl[m * SA_ST + lk] = f2tf32(pa[j] - __uint_as_float(hb));
        }
#pragma unroll
        for (int j = 0; j < 8; j++) {
            int kk = bkb + j * 2;
            uint32_t hb = f2tf32(pb[j]);
            sBh[kk * SB_ST + bn] = hb;
            sBl[kk * SB_ST + bn] = f2tf32(pb[j] - __uint_as_float(hb));
        }
    };

    load_g(0);
    store_s();
    __syncthreads();

    for (int k0 = 0; k0 < LC_; k0 += 16) {
        const bool more = (k0 + 16 < LC_);
        if (more) load_g(k0 + 16);

#pragma unroll
        for (int kc = 0; kc < 16; kc += 8) {
            uint32_t ph[2][4], pl[2][4];
#pragma unroll
            for (int ma = 0; ma < 2; ma++) {
                int mb = warpM * 32 + ma * 16 + qrow;
                ph[ma][0] = sPh[(mb)     * SA_ST + kc + qk];
                ph[ma][1] = sPh[(mb + 8) * SA_ST + kc + qk];
                ph[ma][2] = sPh[(mb)     * SA_ST + kc + qk + 4];
                ph[ma][3] = sPh[(mb + 8) * SA_ST + kc + qk + 4];
                pl[ma][0] = sPl[(mb)     * SA_ST + kc + qk];
                pl[ma][1] = sPl[(mb + 8) * SA_ST + kc + qk];
                pl[ma][2] = sPl[(mb)     * SA_ST + kc + qk + 4];
                pl[ma][3] = sPl[(mb + 8) * SA_ST + kc + qk + 4];
            }
#pragma unroll
            for (int na = 0; na < 4; na++) {
                int nb = warpN * 32 + na * 8 + qrow;
                uint32_t bh[2], bl[2];
                bh[0] = sBh[(kc + qk)     * SB_ST + nb];
                bh[1] = sBh[(kc + qk + 4) * SB_ST + nb];
                bl[0] = sBl[(kc + qk)     * SB_ST + nb];
                bl[1] = sBl[(kc + qk + 4) * SB_ST + nb];
#pragma unroll
                for (int ma = 0; ma < 2; ma++) {
                    mma_tf32(acc[ma][na], ph[ma], bh);
                    mma_tf32(acc[ma][na], ph[ma], bl);
                    mma_tf32(acc[ma][na], pl[ma], bh);
                }
            }
        }

        if (more) {
            __syncthreads();
            store_s();
            __syncthreads();
        }
    }

#pragma unroll
    for (int ma = 0; ma < 2; ma++) {
#pragma unroll
        for (int na = 0; na < 4; na++) {
#pragma unroll
            for (int c = 0; c < 4; c++) {
                int row = m0 + warpM * 32 + ma * 16 + qrow + ((c >= 2) ? 8 : 0);
                int col = warpN * 32 + na * 8 + qk * 2 + (c & 1);
                size_t g = ((size_t)(b * S_ + row)) * F_ + h * HD_ + (col & 63);
                if (col < 64) g_Or[g] = acc[ma][na][c];
                else          g_Oi[g] = acc[ma][na][c];
            }
        }
    }
}

// Fallback: bounded zero-fill so graph capture always has nodes.
__global__ void fill_zero_kernel(float* p, long long n)
{
    long long i = (long long)blockIdx.x * blockDim.x + threadIdx.x;
    if (i < n) p[i] = 0.0f;
}

// ---------------- launch ----------------
extern "C" void kernel_launch(void* const* d_in, const int* in_sizes, int n_in,
                              void* d_out, int out_size)
{
    const long long MN = (long long)B_ * S_ * F_;

    const float* x4M[2]  = {0, 0}; int n4M = 0;
    const float* xctx[2] = {0, 0}; int nctx = 0;
    const float* pmask   = 0;
    const float* wF[4]   = {0, 0, 0, 0}; int nwF = 0;
    const float* wC[4]   = {0, 0, 0, 0}; int nwC = 0;
    const float* bias[8] = {0, 0, 0, 0, 0, 0, 0, 0}; int nb = 0;

    for (int i = 0; i < n_in; i++) {
        const float* p = (const float*)d_in[i];
        long long sz = in_sizes[i];
        if (sz == (long long)B_ * S_ * F_)        { if (n4M < 2) x4M[n4M++] = p; }
        else if (sz == (long long)B_ * LC_ * DC_) { if (nctx < 2) xctx[nctx++] = p; }
        else if (sz == (long long)B_ * LC_)       { pmask = p; }
        else if (sz == (long long)F_ * F_)        { if (nwF < 4) wF[nwF++] = p; }
        else if (sz == (long long)DC_ * F_)       { if (nwC < 4) wC[nwC++] = p; }
        else if (sz == (long long)F_)             { if (nb < 8) bias[nb++] = p; }
    }

    const float* x_r = x4M[0],  *x_i = x4M[1];
    const float* ctx_r = xctx[0], *ctx_i = xctx[1];
    const float* Wqr = wF[0], *Wqi = wF[1], *Wor = wF[2], *Woi = wF[3];
    const float* Wkr = wC[0], *Wki = wC[1], *Wvr = wC[2], *Wvi = wC[3];
    const float* bqr = bias[0], *bqi = bias[1];
    const float* bkr = bias[2], *bki = bias[3];
    const float* bvr = bias[4], *bvi = bias[5];
    const float* bor = bias[6], *boi = bias[7];

    int omode = ((long long)out_size >= 2 * MN) ? 2 : 1;

    if (!x_r || !x_i || !ctx_r || !ctx_i || !Wqr || !Wqi || !Wor || !Woi ||
        !Wkr || !Wki || !Wvr || !Wvi) {
        long long n = (omode == 2) ? 2 * MN : MN;
        fill_zero_kernel<<<(unsigned)((n + 255) / 256), 256>>>((float*)d_out, n);
        return;
    }

    dim3 blk(256);

    // projections
    cgemm_kernel<0><<<dim3(F_ / 128, (B_ * S_) / 64), blk>>>(
        B_ * S_, F_, F_, x_r, x_i, Wqr, Wqi, bqr, bqi, nullptr, 0);
    cgemm_kernel<1><<<dim3(F_ / 128, (B_ * LC_) / 64), blk>>>(
        B_ * LC_, DC_, F_, ctx_r, ctx_i, Wkr, Wki, bkr, bki, nullptr, 0);
    cgemm_kernel<2><<<dim3(F_ / 128, (B_ * LC_) / 64), blk>>>(
        B_ * LC_, DC_, F_, ctx_r, ctx_i, Wvr, Wvi, bvr, bvi, nullptr, 0);

    // attention as 3 specialized kernels
    qk_kernel<<<dim3(LC_ / 128, S_ / 64, B_ * H_), blk>>>();
    softmax_kernel<<<(B_ * H_ * S_) / 8, blk>>>(pmask);
    pv_kernel<<<dim3(1, S_ / 64, B_ * H_), blk>>>();

    // output projection
    cgemm_kernel<3><<<dim3(F_ / 128, (B_ * S_) / 64), blk>>>(
        B_ * S_, F_, F_, nullptr, nullptr, Wor, Woi, bor, boi, (float*)d_out, omode);
}